// round 14
// baseline (speedup 1.0000x reference)
#include <cuda_runtime.h>
#include <math.h>

// Problem constants
#define BB 16
#define TT 512
#define CC 256
#define HH 8
#define ROWS_T (BB*TT)      // 8192
#define ROWS_S (BB*CC)      // 4096

// ---------------- scratch (device globals; no allocation allowed) ----------------
__device__ float g_h[ROWS_T*CC];
__device__ float g_qkv[ROWS_T*3*CC];
__device__ float g_o[ROWS_T*CC];
__device__ float g_x[ROWS_T*CC];
__device__ float g_u[ROWS_T*4*CC];
__device__ float g_to[ROWS_T*CC];
__device__ float g_hs[ROWS_S*TT];
__device__ float g_qks[ROWS_S*2*512];
__device__ float g_x2[ROWS_T*CC];
__device__ float g_wqkv[768*256];     // packed + tf32-rounded
__device__ float g_wqks[1024*512];    // packed + tf32-rounded
__device__ float g_wo[256*256];
__device__ float g_w11[1024*256];
__device__ float g_w12[256*1024];
__device__ float g_w21[1024*256];
__device__ float g_w22[256*1024];

__device__ __forceinline__ unsigned f2tf(float f) {
    unsigned u;
    asm("cvt.rna.tf32.f32 %0, %1;" : "=r"(u) : "f"(f));
    return u;
}
__device__ __forceinline__ float f2tff(float f) { return __uint_as_float(f2tf(f)); }

__device__ __forceinline__ float ex2(float x) {
    float y;
    asm("ex2.approx.f32 %0, %1;" : "=f"(y) : "f"(x));
    return y;
}

__device__ __forceinline__ void mma_tf32(float d[4], const unsigned a[4], const unsigned b[2]) {
    asm("mma.sync.aligned.m16n8k8.row.col.f32.tf32.tf32.f32 "
        "{%0,%1,%2,%3}, {%4,%5,%6,%7}, {%8,%9}, {%0,%1,%2,%3};"
        : "+f"(d[0]), "+f"(d[1]), "+f"(d[2]), "+f"(d[3])
        : "r"(a[0]), "r"(a[1]), "r"(a[2]), "r"(a[3]), "r"(b[0]), "r"(b[1]));
}

__device__ __forceinline__ void cp_async16(unsigned smem_addr, const void* gptr) {
    asm volatile("cp.async.cg.shared.global [%0], [%1], 16;" :: "r"(smem_addr), "l"(gptr));
}
__device__ __forceinline__ void cp_commit() {
    asm volatile("cp.async.commit_group;");
}
template<int N>
__device__ __forceinline__ void cp_wait() {
    asm volatile("cp.async.wait_group %0;" :: "n"(N));
}

// ===== tf32 tensor-core GEMM, cp.async 3-stage pipeline, BK=32:  C = A @ B^T ====
#define BM 128
#define BN 128
#define BK 32
#define TSTR 36
#define STG_F (128 * TSTR)
#define GEMM_SMEM (3 * 2 * STG_F * 4)   // 110592 bytes

template<int BCVT, int CRND>
__global__ void __launch_bounds__(256, 2)
gemm_tc(const float* __restrict__ A, const float* __restrict__ Bw,
        const float* __restrict__ bias, const float* __restrict__ res,
        float* __restrict__ C,
        int M, int N, int K, int lda, int ldb, int ldc,
        int nb2,
        long long sA1, long long sA2, long long sB1, long long sB2,
        long long sC1, long long sC2, int relu)
{
    extern __shared__ float smg[];
    float* Asm = smg;
    float* Bsm = smg + 3 * STG_F;

    int z = blockIdx.z;
    int b1 = z / nb2, b2 = z - b1 * nb2;
    A  += (long long)b1 * sA1 + (long long)b2 * sA2;
    Bw += (long long)b1 * sB1 + (long long)b2 * sB2;
    long long co = (long long)b1 * sC1 + (long long)b2 * sC2;
    C += co;
    if (res) res += co;

    int tid = threadIdx.x;
    int warp = tid >> 5, lane = tid & 31;
    int wm = warp >> 2;
    int wn = warp & 3;
    int gid = lane >> 2, tig = lane & 3;
    int bm = blockIdx.y * BM, bn = blockIdx.x * BN;

    unsigned aBase = (unsigned)__cvta_generic_to_shared(Asm);
    unsigned bBase = (unsigned)__cvta_generic_to_shared(Bsm);

    float acc[4][4][4];
#pragma unroll
    for (int i = 0; i < 4; i++)
#pragma unroll
        for (int j = 0; j < 4; j++)
#pragma unroll
            for (int l = 0; l < 4; l++) acc[i][j][l] = 0.f;

    int nk = K / BK;

#pragma unroll
    for (int s = 0; s < 2; s++) {
        if (s < nk) {
            int k0 = s * BK;
#pragma unroll
            for (int i = 0; i < 4; i++) {
                int idx = tid + 256 * i;
                int r = idx >> 3, c = (idx & 7) * 4;
                cp_async16(aBase + (s * STG_F + r * TSTR + c) * 4,
                           &A[(long long)(bm + r) * lda + k0 + c]);
                cp_async16(bBase + (s * STG_F + r * TSTR + c) * 4,
                           &Bw[(long long)(bn + r) * ldb + k0 + c]);
            }
        }
        cp_commit();
    }
    cp_wait<1>();
    __syncthreads();

    for (int kt = 0; kt < nk; kt++) {
        int cur = kt % 3;
        {
            int sst = (kt + 2) % 3;
            if (kt + 2 < nk) {
                int k0 = (kt + 2) * BK;
#pragma unroll
                for (int i = 0; i < 4; i++) {
                    int idx = tid + 256 * i;
                    int r = idx >> 3, c = (idx & 7) * 4;
                    cp_async16(aBase + (sst * STG_F + r * TSTR + c) * 4,
                               &A[(long long)(bm + r) * lda + k0 + c]);
                    cp_async16(bBase + (sst * STG_F + r * TSTR + c) * 4,
                               &Bw[(long long)(bn + r) * ldb + k0 + c]);
                }
            }
            cp_commit();
        }

        const float* Ac = Asm + cur * STG_F;
        const float* Bc = Bsm + cur * STG_F;
#pragma unroll
        for (int ks = 0; ks < 4; ks++) {
            unsigned af[4][4], bf[4][2];
            int kk = ks * 8;
#pragma unroll
            for (int mt = 0; mt < 4; mt++) {
                int r = wm * 64 + mt * 16 + gid;
                af[mt][0] = f2tf(Ac[r * TSTR + kk + tig]);
                af[mt][1] = f2tf(Ac[(r + 8) * TSTR + kk + tig]);
                af[mt][2] = f2tf(Ac[r * TSTR + kk + tig + 4]);
                af[mt][3] = f2tf(Ac[(r + 8) * TSTR + kk + tig + 4]);
            }
#pragma unroll
            for (int nt = 0; nt < 4; nt++) {
                int n = wn * 32 + nt * 8 + gid;
                if (BCVT) {
                    bf[nt][0] = f2tf(Bc[n * TSTR + kk + tig]);
                    bf[nt][1] = f2tf(Bc[n * TSTR + kk + tig + 4]);
                } else {
                    bf[nt][0] = __float_as_uint(Bc[n * TSTR + kk + tig]);
                    bf[nt][1] = __float_as_uint(Bc[n * TSTR + kk + tig + 4]);
                }
            }
#pragma unroll
            for (int mt = 0; mt < 4; mt++)
#pragma unroll
                for (int nt = 0; nt < 4; nt++)
                    mma_tf32(acc[mt][nt], af[mt], bf[nt]);
        }

        cp_wait<1>();
        __syncthreads();
    }

#pragma unroll
    for (int mt = 0; mt < 4; mt++) {
        int row = bm + wm * 64 + mt * 16 + gid;
#pragma unroll
        for (int nt = 0; nt < 4; nt++) {
            int col = bn + wn * 32 + nt * 8 + tig * 2;
            float v0 = acc[mt][nt][0], v1 = acc[mt][nt][1];
            float v2 = acc[mt][nt][2], v3 = acc[mt][nt][3];
            if (bias) {
                float b0 = bias[col], b1 = bias[col + 1];
                v0 += b0; v1 += b1; v2 += b0; v3 += b1;
            }
            if (res) {
                const float2 r0 = *(const float2*)&res[(long long)row * ldc + col];
                const float2 r1 = *(const float2*)&res[(long long)(row + 8) * ldc + col];
                v0 += r0.x; v1 += r0.y; v2 += r1.x; v3 += r1.y;
            }
            if (relu) {
                v0 = fmaxf(v0, 0.f); v1 = fmaxf(v1, 0.f);
                v2 = fmaxf(v2, 0.f); v3 = fmaxf(v3, 0.f);
            }
            if (CRND) {
                v0 = f2tff(v0); v1 = f2tff(v1);
                v2 = f2tff(v2); v3 = f2tff(v3);
            }
            *(float2*)&C[(long long)row * ldc + col] = make_float2(v0, v1);
            *(float2*)&C[(long long)(row + 8) * ldc + col] = make_float2(v2, v3);
        }
    }
}

// ---------------- weight pack + tf32 pre-round ----------------
__global__ void pack_weights(const float* __restrict__ Wq, const float* __restrict__ Wk,
                             const float* __restrict__ Wv, const float* __restrict__ Wo,
                             const float* __restrict__ Wqs, const float* __restrict__ Wks,
                             const float* __restrict__ w11, const float* __restrict__ w12,
                             const float* __restrict__ w21, const float* __restrict__ w22,
                             float* __restrict__ wqkv, float* __restrict__ wqks,
                             float* __restrict__ owo, float* __restrict__ o11,
                             float* __restrict__ o12, float* __restrict__ o21,
                             float* __restrict__ o22)
{
    int i = blockIdx.x * 256 + threadIdx.x;   // grid covers 262144
    if (i < 65536) {
        wqkv[i]          = f2tff(Wq[i]);
        wqkv[i + 65536]  = f2tff(Wk[i]);
        wqkv[i + 131072] = f2tff(Wv[i]);
        owo[i]           = f2tff(Wo[i]);
    }
    wqks[i]          = f2tff(Wqs[i]);
    wqks[i + 262144] = f2tff(Wks[i]);
    o11[i] = f2tff(w11[i]);
    o12[i] = f2tff(w12[i]);
    o21[i] = f2tff(w21[i]);
    o22[i] = f2tff(w22[i]);
}

// ---------------- LayerNorm: warp per row, shuffle-only ----------------
template<int F4>
__global__ void __launch_bounds__(256)
ln_warp(const float* __restrict__ x, const float* __restrict__ w,
        const float* __restrict__ bp, float* __restrict__ y)
{
    const int D = F4 * 128;
    int warp = threadIdx.x >> 5, lane = threadIdx.x & 31;
    long long row = (long long)blockIdx.x * 8 + warp;
    const float* xr = x + row * D;
    float* yr = y + row * D;

    float4 v[F4];
    float s = 0.f, sq = 0.f;
#pragma unroll
    for (int i = 0; i < F4; i++) {
        v[i] = *(const float4*)&xr[lane * 4 + i * 128];
        s  += v[i].x + v[i].y + v[i].z + v[i].w;
        sq += v[i].x*v[i].x + v[i].y*v[i].y + v[i].z*v[i].z + v[i].w*v[i].w;
    }
#pragma unroll
    for (int off = 16; off; off >>= 1) {
        s  += __shfl_xor_sync(0xffffffffu, s, off);
        sq += __shfl_xor_sync(0xffffffffu, sq, off);
    }
    float mean = s / D;
    float var = sq / D - mean * mean;
    float inv = rsqrtf(var + 1e-6f);
#pragma unroll
    for (int i = 0; i < F4; i++) {
        int c = lane * 4 + i * 128;
        float4 wv = *(const float4*)&w[c];
        float4 bv = *(const float4*)&bp[c];
        float4 r;
        r.x = (v[i].x - mean) * inv * wv.x + bv.x;
        r.y = (v[i].y - mean) * inv * wv.y + bv.y;
        r.z = (v[i].z - mean) * inv * wv.z + bv.z;
        r.w = (v[i].w - mean) * inv * wv.w + bv.w;
        *(float4*)&yr[c] = r;
    }
}

// ============ tensor-core causal flash attention (D=32), cp.async K/V ===========
// qkv pre-rounded to tf32 by producing GEMM. Softmax in exp2 domain.
// __launch_bounds__(256,3): cap regs at 85 -> 3 blocks/SM (smem 3x71.7KB fits).
#define KTILE (64*36)
#define ATTN_SMEM ((4*KTILE + 8*16*68) * 4)
__global__ void __launch_bounds__(256, 3)
attn_tc(const float* __restrict__ qkv, float* __restrict__ O)
{
    extern __shared__ float sm[];
    float* KsB = sm;
    float* VsB = sm + 2 * KTILE;
    int qb = gridDim.x - 1 - blockIdx.x;   // heaviest blocks first
    int bh = blockIdx.y;
    int b = bh >> 3, hh = bh & 7;
    int tid = threadIdx.x, warp = tid >> 5, lane = tid & 31;
    int gid = lane >> 2, tig = lane & 3;
    float* Pw = sm + 4 * KTILE + warp * 16 * 68;

    unsigned kBase = (unsigned)__cvta_generic_to_shared(KsB);
    unsigned vBase = (unsigned)__cvta_generic_to_shared(VsB);

    int qrow = qb * 128 + warp * 16;
    const float* Qb = qkv + (long long)(b * TT + qrow) * 768 + hh * 32;

    unsigned qf[4][4];
#pragma unroll
    for (int ks = 0; ks < 4; ks++) {
        qf[ks][0] = __float_as_uint(Qb[gid * 768 + ks * 8 + tig]);
        qf[ks][1] = __float_as_uint(Qb[(gid + 8) * 768 + ks * 8 + tig]);
        qf[ks][2] = __float_as_uint(Qb[gid * 768 + ks * 8 + tig + 4]);
        qf[ks][3] = __float_as_uint(Qb[(gid + 8) * 768 + ks * 8 + tig + 4]);
    }

    float m0 = -1e30f, m1 = -1e30f, l0 = 0.f, l1 = 0.f;
    float oacc[4][4];
#pragma unroll
    for (int i = 0; i < 4; i++)
#pragma unroll
        for (int j = 0; j < 4; j++) oacc[i][j] = 0.f;

    // scale * log2(e):  (1/sqrt(32)) * 1.4426950408889634
    const float scale2 = 0.2550500337255891f;
    int kbmax = 2 * qb + 1;

    {
#pragma unroll
        for (int i = 0; i < 2; i++) {
            int idx = tid + 256 * i;
            int r = idx >> 3, c = (idx & 7) * 4;
            const float* p = qkv + (long long)(b * TT + r) * 768 + 256 + hh * 32 + c;
            cp_async16(kBase + (r * 36 + c) * 4, p);
            cp_async16(vBase + (r * 36 + c) * 4, p + 256);
        }
        cp_commit();
    }

    for (int kb = 0; kb <= kbmax; kb++) {
        int cur = kb & 1, nxt = cur ^ 1;
        cp_wait<0>();
        __syncthreads();
        if (kb < kbmax) {
#pragma unroll
            for (int i = 0; i < 2; i++) {
                int idx = tid + 256 * i;
                int r = idx >> 3, c = (idx & 7) * 4;
                const float* p = qkv + (long long)(b * TT + (kb + 1) * 64 + r) * 768 + 256 + hh * 32 + c;
                cp_async16(kBase + (nxt * KTILE + r * 36 + c) * 4, p);
                cp_async16(vBase + (nxt * KTILE + r * 36 + c) * 4, p + 256);
            }
        }
        cp_commit();

        if (kb * 64 > qrow + 15) continue;

        const float* Ks = KsB + cur * KTILE;
        const float* Vs = VsB + cur * KTILE;

        float sacc[8][4];
#pragma unroll
        for (int nt = 0; nt < 8; nt++)
#pragma unroll
            for (int c = 0; c < 4; c++) sacc[nt][c] = 0.f;
#pragma unroll
        for (int ks = 0; ks < 4; ks++) {
#pragma unroll
            for (int nt = 0; nt < 8; nt++) {
                unsigned bb[2];
                bb[0] = __float_as_uint(Ks[(nt * 8 + gid) * 36 + ks * 8 + tig]);
                bb[1] = __float_as_uint(Ks[(nt * 8 + gid) * 36 + ks * 8 + tig + 4]);
                mma_tf32(sacc[nt], qf[ks], bb);
            }
        }

        bool diag = (kb * 64 + 63 > qrow);
        int row0 = qrow + gid, row1 = row0 + 8;
        float rmax0 = -1e30f, rmax1 = -1e30f;
#pragma unroll
        for (int nt = 0; nt < 8; nt++) {
            int colb = kb * 64 + nt * 8 + tig * 2;
            float s0 = sacc[nt][0] * scale2;   // log2-domain scores
            float s1 = sacc[nt][1] * scale2;
            float s2 = sacc[nt][2] * scale2;
            float s3 = sacc[nt][3] * scale2;
            if (diag) {
                if (colb     > row0) s0 = -1e30f;
                if (colb + 1 > row0) s1 = -1e30f;
                if (colb     > row1) s2 = -1e30f;
                if (colb + 1 > row1) s3 = -1e30f;
            }
            sacc[nt][0] = s0; sacc[nt][1] = s1; sacc[nt][2] = s2; sacc[nt][3] = s3;
            rmax0 = fmaxf(rmax0, fmaxf(s0, s1));
            rmax1 = fmaxf(rmax1, fmaxf(s2, s3));
        }
        rmax0 = fmaxf(rmax0, __shfl_xor_sync(0xffffffffu, rmax0, 1));
        rmax0 = fmaxf(rmax0, __shfl_xor_sync(0xffffffffu, rmax0, 2));
        rmax1 = fmaxf(rmax1, __shfl_xor_sync(0xffffffffu, rmax1, 1));
        rmax1 = fmaxf(rmax1, __shfl_xor_sync(0xffffffffu, rmax1, 2));

        float newm0 = fmaxf(m0, rmax0), newm1 = fmaxf(m1, rmax1);
        float a0 = ex2(m0 - newm0), a1 = ex2(m1 - newm1);
        m0 = newm0; m1 = newm1;

        float ls0 = 0.f, ls1 = 0.f;
#pragma unroll
        for (int nt = 0; nt < 8; nt++) {
            float p0 = ex2(sacc[nt][0] - newm0);
            float p1 = ex2(sacc[nt][1] - newm0);
            float p2 = ex2(sacc[nt][2] - newm1);
            float p3 = ex2(sacc[nt][3] - newm1);
            ls0 += p0 + p1; ls1 += p2 + p3;
            Pw[gid * 68 + nt * 8 + tig * 2]           = p0;
            Pw[gid * 68 + nt * 8 + tig * 2 + 1]       = p1;
            Pw[(gid + 8) * 68 + nt * 8 + tig * 2]     = p2;
            Pw[(gid + 8) * 68 + nt * 8 + tig * 2 + 1] = p3;
        }
        ls0 += __shfl_xor_sync(0xffffffffu, ls0, 1);
        ls0 += __shfl_xor_sync(0xffffffffu, ls0, 2);
        ls1 += __shfl_xor_sync(0xffffffffu, ls1, 1);
        ls1 += __shfl_xor_sync(0xffffffffu, ls1, 2);
        l0 = l0 * a0 + ls0;
        l1 = l1 * a1 + ls1;
#pragma unroll
        for (int nt = 0; nt < 4; nt++) {
            oacc[nt][0] *= a0; oacc[nt][1] *= a0;
            oacc[nt][2] *= a1; oacc[nt][3] *= a1;
        }
        __syncwarp();

#pragma unroll
        for (int ks2 = 0; ks2 < 8; ks2++) {
            unsigned af[4];
            af[0] = __float_as_uint(Pw[gid * 68 + ks2 * 8 + tig]);
            af[1] = __float_as_uint(Pw[(gid + 8) * 68 + ks2 * 8 + tig]);
            af[2] = __float_as_uint(Pw[gid * 68 + ks2 * 8 + tig + 4]);
            af[3] = __float_as_uint(Pw[(gid + 8) * 68 + ks2 * 8 + tig + 4]);
#pragma unroll
            for (int nt2 = 0; nt2 < 4; nt2++) {
                unsigned bb[2];
                bb[0] = __float_as_uint(Vs[(ks2 * 8 + tig) * 36 + nt2 * 8 + gid]);
                bb[1] = __float_as_uint(Vs[(ks2 * 8 + tig + 4) * 36 + nt2 * 8 + gid]);
                mma_tf32(oacc[nt2], af, bb);
            }
        }
        __syncwarp();
    }

    float invl0 = 1.f / l0, invl1 = 1.f / l1;
#pragma unroll
    for (int nt2 = 0; nt2 < 4; nt2++) {
        int col = hh * 32 + nt2 * 8 + tig * 2;
        long long o0 = (long long)(b * TT + qrow + gid) * CC + col;
        long long o1 = (long long)(b * TT + qrow + gid + 8) * CC + col;
        *(float2*)&O[o0] = make_float2(oacc[nt2][0] * invl0, oacc[nt2][1] * invl0);
        *(float2*)&O[o1] = make_float2(oacc[nt2][2] * invl1, oacc[nt2][3] * invl1);
    }
}

// ============ fused spatial scores + softmax + head-mean ============
// qks pre-rounded to tf32 by producing GEMM -> raw loads, no cvt.
__global__ void __launch_bounds__(256)
spatial_sw(const float* __restrict__ qks, float* __restrict__ sw)
{
    int bid = blockIdx.x;
    int b = bid >> 4, ct = bid & 15;
    int c0 = ct * 16;
    int tid = threadIdx.x, warp = tid >> 5, lane = tid & 31;
    int gid = lane >> 2, tig = lane & 3;

    __shared__ float As[16][68];
    __shared__ float Bs[256][20];
    __shared__ float redA[8][17];
    __shared__ float redB[8][17];

    float macc[4][4];
#pragma unroll
    for (int i = 0; i < 4; i++)
#pragma unroll
        for (int j = 0; j < 4; j++) macc[i][j] = 0.f;

    // (1/sqrt(64)) * log2(e)
    const float scale2 = 0.18033688011112043f;

    for (int h = 0; h < 8; h++) {
        {
            int r = tid >> 4, c4 = tid & 15;
            float4 v = *(const float4*)&qks[(long long)(b * 256 + c0 + r) * 1024 + h * 64 + c4 * 4];
            *(float4*)&As[r][c4 * 4] = v;
        }

        float sacc[4][4];
#pragma unroll
        for (int i = 0; i < 4; i++)
#pragma unroll
            for (int j = 0; j < 4; j++) sacc[i][j] = 0.f;

        for (int kt = 0; kt < 4; kt++) {
#pragma unroll
            for (int i = 0; i < 4; i++) {
                int idx = tid + 256 * i;
                int e = idx >> 2, c4 = idx & 3;
                float4 v = *(const float4*)&qks[(long long)(b * 256 + e) * 1024 + 512 + h * 64 + kt * 16 + c4 * 4];
                *(float4*)&Bs[e][c4 * 4] = v;
            }
            __syncthreads();
#pragma unroll
            for (int ks = 0; ks < 2; ks++) {
                int kk = kt * 16 + ks * 8;
                unsigned af[4];
                af[0] = __float_as_uint(As[gid][kk + tig]);
                af[1] = __float_as_uint(As[gid + 8][kk + tig]);
                af[2] = __float_as_uint(As[gid][kk + tig + 4]);
                af[3] = __float_as_uint(As[gid + 8][kk + tig + 4]);
#pragma unroll
                for (int nt = 0; nt < 4; nt++) {
                    int n = warp * 32 + nt * 8 + gid;
                    unsigned bb[2];
                    bb[0] = __float_as_uint(Bs[n][ks * 8 + tig]);
                    bb[1] = __float_as_uint(Bs[n][ks * 8 + tig + 4]);
                    mma_tf32(sacc[nt], af, bb);
                }
            }
            __syncthreads();
        }

        float m0 = -1e30f, m1 = -1e30f;
#pragma unroll
        for (int nt = 0; nt < 4; nt++) {
            sacc[nt][0] *= scale2; sacc[nt][1] *= scale2;
            sacc[nt][2] *= scale2; sacc[nt][3] *= scale2;
            m0 = fmaxf(m0, fmaxf(sacc[nt][0], sacc[nt][1]));
            m1 = fmaxf(m1, fmaxf(sacc[nt][2], sacc[nt][3]));
        }
        m0 = fmaxf(m0, __shfl_xor_sync(0xffffffffu, m0, 1));
        m0 = fmaxf(m0, __shfl_xor_sync(0xffffffffu, m0, 2));
        m1 = fmaxf(m1, __shfl_xor_sync(0xffffffffu, m1, 1));
        m1 = fmaxf(m1, __shfl_xor_sync(0xffffffffu, m1, 2));
        if (tig == 0) { redA[warp][gid] = m0; redA[warp][gid + 8] = m1; }
        __syncthreads();
        float gm0 = -1e30f, gm1 = -1e30f;
#pragma unroll
        for (int w2 = 0; w2 < 8; w2++) {
            gm0 = fmaxf(gm0, redA[w2][gid]);
            gm1 = fmaxf(gm1, redA[w2][gid + 8]);
        }
        float ps0 = 0.f, ps1 = 0.f;
#pragma unroll
        for (int nt = 0; nt < 4; nt++) {
            sacc[nt][0] = ex2(sacc[nt][0] - gm0);
            sacc[nt][1] = ex2(sacc[nt][1] - gm0);
            sacc[nt][2] = ex2(sacc[nt][2] - gm1);
            sacc[nt][3] = ex2(sacc[nt][3] - gm1);
            ps0 += sacc[nt][0] + sacc[nt][1];
            ps1 += sacc[nt][2] + sacc[nt][3];
        }
        ps0 += __shfl_xor_sync(0xffffffffu, ps0, 1);
        ps0 += __shfl_xor_sync(0xffffffffu, ps0, 2);
        ps1 += __shfl_xor_sync(0xffffffffu, ps1, 1);
        ps1 += __shfl_xor_sync(0xffffffffu, ps1, 2);
        if (tig == 0) { redB[warp][gid] = ps0; redB[warp][gid + 8] = ps1; }
        __syncthreads();
        float gs0 = 0.f, gs1 = 0.f;
#pragma unroll
        for (int w2 = 0; w2 < 8; w2++) {
            gs0 += redB[w2][gid];
            gs1 += redB[w2][gid + 8];
        }
        float inv0 = 1.f / (8.f * gs0), inv1 = 1.f / (8.f * gs1);
#pragma unroll
        for (int nt = 0; nt < 4; nt++) {
            macc[nt][0] += sacc[nt][0] * inv0;
            macc[nt][1] += sacc[nt][1] * inv0;
            macc[nt][2] += sacc[nt][2] * inv1;
            macc[nt][3] += sacc[nt][3] * inv1;
        }
        __syncthreads();
    }

#pragma unroll
    for (int nt = 0; nt < 4; nt++) {
        int col = warp * 32 + nt * 8 + tig * 2;
        *(float2*)&sw[(long long)(b * 256 + c0 + gid) * 256 + col] =
            make_float2(macc[nt][0], macc[nt][1]);
        *(float2*)&sw[(long long)(b * 256 + c0 + gid + 8) * 256 + col] =
            make_float2(macc[nt][2], macc[nt][3]);
    }
}

// ---------------- host launch ----------------
static void gemm(const float* A, const float* Bw, const float* bias, const float* res, float* C,
                 int M, int N, int K, int lda, int ldb, int ldc,
                 int nbatch, int nb2,
                 long long sA1, long long sA2, long long sB1, long long sB2,
                 long long sC1, long long sC2, int relu, int bcvt, int crnd)
{
    dim3 grid(N / BN, M / BM, nbatch);
    if (bcvt)
        gemm_tc<1,0><<<grid, 256, GEMM_SMEM>>>(A, Bw, bias, res, C, M, N, K, lda, ldb, ldc,
                                               nb2, sA1, sA2, sB1, sB2, sC1, sC2, relu);
    else if (crnd)
        gemm_tc<0,1><<<grid, 256, GEMM_SMEM>>>(A, Bw, bias, res, C, M, N, K, lda, ldb, ldc,
                                               nb2, sA1, sA2, sB1, sB2, sC1, sC2, relu);
    else
        gemm_tc<0,0><<<grid, 256, GEMM_SMEM>>>(A, Bw, bias, res, C, M, N, K, lda, ldb, ldc,
                                               nb2, sA1, sA2, sB1, sB2, sC1, sC2, relu);
}

extern "C" void kernel_launch(void* const* d_in, const int* in_sizes, int n_in,
                              void* d_out, int out_size)
{
    const float* x_T     = (const float*)d_in[0];
    const float* x_S     = (const float*)d_in[1];
    const float* Wq_t    = (const float*)d_in[2];
    const float* Wk_t    = (const float*)d_in[3];
    const float* Wv_t    = (const float*)d_in[4];
    const float* Wo      = (const float*)d_in[5];
    const float* Wq_s    = (const float*)d_in[6];
    const float* Wk_s    = (const float*)d_in[7];
    const float* ff1_w1  = (const float*)d_in[8];
    const float* ff1_b1  = (const float*)d_in[9];
    const float* ff1_w2  = (const float*)d_in[10];
    const float* ff1_b2  = (const float*)d_in[11];
    const float* ff2_w1  = (const float*)d_in[12];
    const float* ff2_b1  = (const float*)d_in[13];
    const float* ff2_w2  = (const float*)d_in[14];
    const float* ff2_b2  = (const float*)d_in[15];
    const float* t_ln1_w = (const float*)d_in[16];
    const float* t_ln1_b = (const float*)d_in[17];
    const float* t_ln2_w = (const float*)d_in[18];
    const float* t_ln2_b = (const float*)d_in[19];
    const float* s_ln1_w = (const float*)d_in[20];
    const float* s_ln1_b = (const float*)d_in[21];
    const float* fus_ln_w= (const float*)d_in[22];
    const float* fus_ln_b= (const float*)d_in[23];

    float *h, *qkv, *o, *x, *u, *to, *hs, *qks, *x2;
    float *wqkv, *wqks, *wo, *w11, *w12, *w21, *w22;
    cudaGetSymbolAddress((void**)&h,    g_h);
    cudaGetSymbolAddress((void**)&qkv,  g_qkv);
    cudaGetSymbolAddress((void**)&o,    g_o);
    cudaGetSymbolAddress((void**)&x,    g_x);
    cudaGetSymbolAddress((void**)&u,    g_u);
    cudaGetSymbolAddress((void**)&to,   g_to);
    cudaGetSymbolAddress((void**)&hs,   g_hs);
    cudaGetSymbolAddress((void**)&qks,  g_qks);
    cudaGetSymbolAddress((void**)&x2,   g_x2);
    cudaGetSymbolAddress((void**)&wqkv, g_wqkv);
    cudaGetSymbolAddress((void**)&wqks, g_wqks);
    cudaGetSymbolAddress((void**)&wo,   g_wo);
    cudaGetSymbolAddress((void**)&w11,  g_w11);
    cudaGetSymbolAddress((void**)&w12,  g_w12);
    cudaGetSymbolAddress((void**)&w21,  g_w21);
    cudaGetSymbolAddress((void**)&w22,  g_w22);

    float* out = (float*)d_out;                 // [B,T,C]
    float* sw  = out + (long long)ROWS_T * CC;  // spatial_weights [B,C,C]

    cudaFuncSetAttribute(gemm_tc<0,0>, cudaFuncAttributeMaxDynamicSharedMemorySize, GEMM_SMEM);
    cudaFuncSetAttribute(gemm_tc<0,1>, cudaFuncAttributeMaxDynamicSharedMemorySize, GEMM_SMEM);
    cudaFuncSetAttribute(gemm_tc<1,0>, cudaFuncAttributeMaxDynamicSharedMemorySize, GEMM_SMEM);
    cudaFuncSetAttribute(attn_tc, cudaFuncAttributeMaxDynamicSharedMemorySize, ATTN_SMEM);

    // pack + pre-round weights (one node)
    pack_weights<<<262144/256, 256>>>(Wq_t, Wk_t, Wv_t, Wo, Wq_s, Wk_s,
                                      ff1_w1, ff1_w2, ff2_w1, ff2_w2,
                                      wqkv, wqks, wo, w11, w12, w21, w22);

    // ---- temporal branch ----
    ln_warp<2><<<ROWS_T/8, 256>>>(x_T, t_ln1_w, t_ln1_b, h);
    gemm(h, wqkv, 0, 0, qkv, ROWS_T, 768, CC, CC, CC, 768, 1,1, 0,0,0,0,0,0, 0, 0, 1);
    attn_tc<<<dim3(TT/128, BB*HH), 256, ATTN_SMEM>>>(qkv, o);
    gemm(o, wo, 0, x_T, x, ROWS_T, CC, CC, CC, CC, CC, 1,1, 0,0,0,0,0,0, 0, 0, 0);
    ln_warp<2><<<ROWS_T/8, 256>>>(x, t_ln2_w, t_ln2_b, h);
    gemm(h, w11, ff1_b1, 0, u,  ROWS_T, 4*CC, CC, CC, CC, 4*CC, 1,1, 0,0,0,0,0,0, 1, 0, 0);
    gemm(u, w12, ff1_b2, x, to, ROWS_T, CC, 4*CC, 4*CC, 4*CC, CC, 1,1, 0,0,0,0,0,0, 0, 0, 0);

    // ---- spatial branch ----
    ln_warp<4><<<ROWS_S/8, 256>>>(x_S, s_ln1_w, s_ln1_b, hs);
    gemm(hs, wqks, 0, 0, qks, ROWS_S, 1024, TT, TT, TT, 1024, 1,1, 0,0,0,0,0,0, 0, 0, 1);
    spatial_sw<<<256, 256>>>(qks, sw);

    // ---- fusion: x2 = TO + TO @ sw^T (batched over b; sw needs cvt) ----
    gemm(to, sw, 0, to, x2, TT, CC, CC, CC, CC, CC,
         BB, 1,
         (long long)TT*CC, 0, (long long)CC*CC, 0, (long long)TT*CC, 0, 0, 1, 0);

    // ---- FFN2 -> out ----
    ln_warp<2><<<ROWS_T/8, 256>>>(x2, fus_ln_w, fus_ln_b, h);
    gemm(h, w21, ff2_b1, 0, u, ROWS_T, 4*CC, CC, CC, CC, 4*CC, 1,1, 0,0,0,0,0,0, 1, 0, 0);
    gemm(u, w22, ff2_b2, x2, out, ROWS_T, CC, 4*CC, 4*CC, 4*CC, CC, 1,1, 0,0,0,0,0,0, 0, 0, 0);
}

// round 16
// speedup vs baseline: 1.0458x; 1.0458x over previous
#include <cuda_runtime.h>
#include <math.h>

// Problem constants
#define BB 16
#define TT 512
#define CC 256
#define HH 8
#define ROWS_T (BB*TT)      // 8192
#define ROWS_S (BB*CC)      // 4096

// ---------------- scratch (device globals; no allocation allowed) ----------------
__device__ float g_h[ROWS_T*CC];
__device__ float g_qkv[ROWS_T*3*CC];
__device__ float g_o[ROWS_T*CC];
__device__ float g_x[ROWS_T*CC];
__device__ float g_u[ROWS_T*4*CC];
__device__ float g_to[ROWS_T*CC];
__device__ float g_hs[ROWS_S*TT];
__device__ float g_qks[ROWS_S*2*512];
__device__ float g_x2[ROWS_T*CC];
__device__ float g_wqkv[768*256];     // packed + tf32-rounded
__device__ float g_wqks[1024*512];    // packed + tf32-rounded
__device__ float g_wo[256*256];
__device__ float g_w11[1024*256];
__device__ float g_w12[256*1024];
__device__ float g_w21[1024*256];
__device__ float g_w22[256*1024];

__device__ __forceinline__ unsigned f2tf(float f) {
    unsigned u;
    asm("cvt.rna.tf32.f32 %0, %1;" : "=r"(u) : "f"(f));
    return u;
}
__device__ __forceinline__ float f2tff(float f) { return __uint_as_float(f2tf(f)); }

__device__ __forceinline__ float ex2(float x) {
    float y;
    asm("ex2.approx.f32 %0, %1;" : "=f"(y) : "f"(x));
    return y;
}

__device__ __forceinline__ void mma_tf32(float d[4], const unsigned a[4], const unsigned b[2]) {
    asm("mma.sync.aligned.m16n8k8.row.col.f32.tf32.tf32.f32 "
        "{%0,%1,%2,%3}, {%4,%5,%6,%7}, {%8,%9}, {%0,%1,%2,%3};"
        : "+f"(d[0]), "+f"(d[1]), "+f"(d[2]), "+f"(d[3])
        : "r"(a[0]), "r"(a[1]), "r"(a[2]), "r"(a[3]), "r"(b[0]), "r"(b[1]));
}

__device__ __forceinline__ void cp_async16(unsigned smem_addr, const void* gptr) {
    asm volatile("cp.async.cg.shared.global [%0], [%1], 16;" :: "r"(smem_addr), "l"(gptr));
}
__device__ __forceinline__ void cp_commit() {
    asm volatile("cp.async.commit_group;");
}
template<int N>
__device__ __forceinline__ void cp_wait() {
    asm volatile("cp.async.wait_group %0;" :: "n"(N));
}

// ===== tf32 tensor-core GEMM, cp.async 3-stage pipeline, BK=32:  C = A @ B^T ====
// ACVT/BCVT: whether A/B need tf32 rounding on fragment read (0 = pre-rounded).
// CRND: round C to tf32 on store (for consumers that read C as a GEMM/MMA input).
#define BM 128
#define BN 128
#define BK 32
#define TSTR 36
#define STG_F (128 * TSTR)
#define GEMM_SMEM (3 * 2 * STG_F * 4)   // 110592 bytes

template<int ACVT, int BCVT, int CRND>
__global__ void __launch_bounds__(256, 2)
gemm_tc(const float* __restrict__ A, const float* __restrict__ Bw,
        const float* __restrict__ bias, const float* __restrict__ res,
        float* __restrict__ C,
        int M, int N, int K, int lda, int ldb, int ldc,
        int nb2,
        long long sA1, long long sA2, long long sB1, long long sB2,
        long long sC1, long long sC2, int relu)
{
    extern __shared__ float smg[];
    float* Asm = smg;
    float* Bsm = smg + 3 * STG_F;

    int z = blockIdx.z;
    int b1 = z / nb2, b2 = z - b1 * nb2;
    A  += (long long)b1 * sA1 + (long long)b2 * sA2;
    Bw += (long long)b1 * sB1 + (long long)b2 * sB2;
    long long co = (long long)b1 * sC1 + (long long)b2 * sC2;
    C += co;
    if (res) res += co;

    int tid = threadIdx.x;
    int warp = tid >> 5, lane = tid & 31;
    int wm = warp >> 2;
    int wn = warp & 3;
    int gid = lane >> 2, tig = lane & 3;
    int bm = blockIdx.y * BM, bn = blockIdx.x * BN;

    unsigned aBase = (unsigned)__cvta_generic_to_shared(Asm);
    unsigned bBase = (unsigned)__cvta_generic_to_shared(Bsm);

    float acc[4][4][4];
#pragma unroll
    for (int i = 0; i < 4; i++)
#pragma unroll
        for (int j = 0; j < 4; j++)
#pragma unroll
            for (int l = 0; l < 4; l++) acc[i][j][l] = 0.f;

    int nk = K / BK;

#pragma unroll
    for (int s = 0; s < 2; s++) {
        if (s < nk) {
            int k0 = s * BK;
#pragma unroll
            for (int i = 0; i < 4; i++) {
                int idx = tid + 256 * i;
                int r = idx >> 3, c = (idx & 7) * 4;
                cp_async16(aBase + (s * STG_F + r * TSTR + c) * 4,
                           &A[(long long)(bm + r) * lda + k0 + c]);
                cp_async16(bBase + (s * STG_F + r * TSTR + c) * 4,
                           &Bw[(long long)(bn + r) * ldb + k0 + c]);
            }
        }
        cp_commit();
    }
    cp_wait<1>();
    __syncthreads();

    for (int kt = 0; kt < nk; kt++) {
        int cur = kt % 3;
        {
            int sst = (kt + 2) % 3;
            if (kt + 2 < nk) {
                int k0 = (kt + 2) * BK;
#pragma unroll
                for (int i = 0; i < 4; i++) {
                    int idx = tid + 256 * i;
                    int r = idx >> 3, c = (idx & 7) * 4;
                    cp_async16(aBase + (sst * STG_F + r * TSTR + c) * 4,
                               &A[(long long)(bm + r) * lda + k0 + c]);
                    cp_async16(bBase + (sst * STG_F + r * TSTR + c) * 4,
                               &Bw[(long long)(bn + r) * ldb + k0 + c]);
                }
            }
            cp_commit();
        }

        const float* Ac = Asm + cur * STG_F;
        const float* Bc = Bsm + cur * STG_F;
#pragma unroll
        for (int ks = 0; ks < 4; ks++) {
            unsigned af[4][4], bf[4][2];
            int kk = ks * 8;
#pragma unroll
            for (int mt = 0; mt < 4; mt++) {
                int r = wm * 64 + mt * 16 + gid;
                if (ACVT) {
                    af[mt][0] = f2tf(Ac[r * TSTR + kk + tig]);
                    af[mt][1] = f2tf(Ac[(r + 8) * TSTR + kk + tig]);
                    af[mt][2] = f2tf(Ac[r * TSTR + kk + tig + 4]);
                    af[mt][3] = f2tf(Ac[(r + 8) * TSTR + kk + tig + 4]);
                } else {
                    af[mt][0] = __float_as_uint(Ac[r * TSTR + kk + tig]);
                    af[mt][1] = __float_as_uint(Ac[(r + 8) * TSTR + kk + tig]);
                    af[mt][2] = __float_as_uint(Ac[r * TSTR + kk + tig + 4]);
                    af[mt][3] = __float_as_uint(Ac[(r + 8) * TSTR + kk + tig + 4]);
                }
            }
#pragma unroll
            for (int nt = 0; nt < 4; nt++) {
                int n = wn * 32 + nt * 8 + gid;
                if (BCVT) {
                    bf[nt][0] = f2tf(Bc[n * TSTR + kk + tig]);
                    bf[nt][1] = f2tf(Bc[n * TSTR + kk + tig + 4]);
                } else {
                    bf[nt][0] = __float_as_uint(Bc[n * TSTR + kk + tig]);
                    bf[nt][1] = __float_as_uint(Bc[n * TSTR + kk + tig + 4]);
                }
            }
#pragma unroll
            for (int mt = 0; mt < 4; mt++)
#pragma unroll
                for (int nt = 0; nt < 4; nt++)
                    mma_tf32(acc[mt][nt], af[mt], bf[nt]);
        }

        cp_wait<1>();
        __syncthreads();
    }

#pragma unroll
    for (int mt = 0; mt < 4; mt++) {
        int row = bm + wm * 64 + mt * 16 + gid;
#pragma unroll
        for (int nt = 0; nt < 4; nt++) {
            int col = bn + wn * 32 + nt * 8 + tig * 2;
            float v0 = acc[mt][nt][0], v1 = acc[mt][nt][1];
            float v2 = acc[mt][nt][2], v3 = acc[mt][nt][3];
            if (bias) {
                float b0 = bias[col], b1 = bias[col + 1];
                v0 += b0; v1 += b1; v2 += b0; v3 += b1;
            }
            if (res) {
                const float2 r0 = *(const float2*)&res[(long long)row * ldc + col];
                const float2 r1 = *(const float2*)&res[(long long)(row + 8) * ldc + col];
                v0 += r0.x; v1 += r0.y; v2 += r1.x; v3 += r1.y;
            }
            if (relu) {
                v0 = fmaxf(v0, 0.f); v1 = fmaxf(v1, 0.f);
                v2 = fmaxf(v2, 0.f); v3 = fmaxf(v3, 0.f);
            }
            if (CRND) {
                v0 = f2tff(v0); v1 = f2tff(v1);
                v2 = f2tff(v2); v3 = f2tff(v3);
            }
            *(float2*)&C[(long long)row * ldc + col] = make_float2(v0, v1);
            *(float2*)&C[(long long)(row + 8) * ldc + col] = make_float2(v2, v3);
        }
    }
}

// ---------------- weight pack + tf32 pre-round ----------------
__global__ void pack_weights(const float* __restrict__ Wq, const float* __restrict__ Wk,
                             const float* __restrict__ Wv, const float* __restrict__ Wo,
                             const float* __restrict__ Wqs, const float* __restrict__ Wks,
                             const float* __restrict__ w11, const float* __restrict__ w12,
                             const float* __restrict__ w21, const float* __restrict__ w22,
                             float* __restrict__ wqkv, float* __restrict__ wqks,
                             float* __restrict__ owo, float* __restrict__ o11,
                             float* __restrict__ o12, float* __restrict__ o21,
                             float* __restrict__ o22)
{
    int i = blockIdx.x * 256 + threadIdx.x;   // grid covers 262144
    if (i < 65536) {
        wqkv[i]          = f2tff(Wq[i]);
        wqkv[i + 65536]  = f2tff(Wk[i]);
        wqkv[i + 131072] = f2tff(Wv[i]);
        owo[i]           = f2tff(Wo[i]);
    }
    wqks[i]          = f2tff(Wqs[i]);
    wqks[i + 262144] = f2tff(Wks[i]);
    o11[i] = f2tff(w11[i]);
    o12[i] = f2tff(w12[i]);
    o21[i] = f2tff(w21[i]);
    o22[i] = f2tff(w22[i]);
}

// ---------------- LayerNorm: warp per row, tf32-rounded output ----------------
template<int F4>
__global__ void __launch_bounds__(256)
ln_warp(const float* __restrict__ x, const float* __restrict__ w,
        const float* __restrict__ bp, float* __restrict__ y)
{
    const int D = F4 * 128;
    int warp = threadIdx.x >> 5, lane = threadIdx.x & 31;
    long long row = (long long)blockIdx.x * 8 + warp;
    const float* xr = x + row * D;
    float* yr = y + row * D;

    float4 v[F4];
    float s = 0.f, sq = 0.f;
#pragma unroll
    for (int i = 0; i < F4; i++) {
        v[i] = *(const float4*)&xr[lane * 4 + i * 128];
        s  += v[i].x + v[i].y + v[i].z + v[i].w;
        sq += v[i].x*v[i].x + v[i].y*v[i].y + v[i].z*v[i].z + v[i].w*v[i].w;
    }
#pragma unroll
    for (int off = 16; off; off >>= 1) {
        s  += __shfl_xor_sync(0xffffffffu, s, off);
        sq += __shfl_xor_sync(0xffffffffu, sq, off);
    }
    float mean = s / D;
    float var = sq / D - mean * mean;
    float inv = rsqrtf(var + 1e-6f);
#pragma unroll
    for (int i = 0; i < F4; i++) {
        int c = lane * 4 + i * 128;
        float4 wv = *(const float4*)&w[c];
        float4 bv = *(const float4*)&bp[c];
        float4 r;
        r.x = f2tff((v[i].x - mean) * inv * wv.x + bv.x);
        r.y = f2tff((v[i].y - mean) * inv * wv.y + bv.y);
        r.z = f2tff((v[i].z - mean) * inv * wv.z + bv.z);
        r.w = f2tff((v[i].w - mean) * inv * wv.w + bv.w);
        *(float4*)&yr[c] = r;
    }
}

// ============ tensor-core causal flash attention (D=32), cp.async K/V ===========
// qkv pre-rounded to tf32 by producing GEMM. Softmax in exp2 domain.
// Output o rounded to tf32 (only consumed as Wo-GEMM A operand).
#define KTILE (64*36)
#define ATTN_SMEM ((4*KTILE + 8*16*68) * 4)
__global__ void __launch_bounds__(256)
attn_tc(const float* __restrict__ qkv, float* __restrict__ O)
{
    extern __shared__ float sm[];
    float* KsB = sm;
    float* VsB = sm + 2 * KTILE;
    int qb = gridDim.x - 1 - blockIdx.x;   // heaviest blocks first
    int bh = blockIdx.y;
    int b = bh >> 3, hh = bh & 7;
    int tid = threadIdx.x, warp = tid >> 5, lane = tid & 31;
    int gid = lane >> 2, tig = lane & 3;
    float* Pw = sm + 4 * KTILE + warp * 16 * 68;

    unsigned kBase = (unsigned)__cvta_generic_to_shared(KsB);
    unsigned vBase = (unsigned)__cvta_generic_to_shared(VsB);

    int qrow = qb * 128 + warp * 16;
    const float* Qb = qkv + (long long)(b * TT + qrow) * 768 + hh * 32;

    unsigned qf[4][4];
#pragma unroll
    for (int ks = 0; ks < 4; ks++) {
        qf[ks][0] = __float_as_uint(Qb[gid * 768 + ks * 8 + tig]);
        qf[ks][1] = __float_as_uint(Qb[(gid + 8) * 768 + ks * 8 + tig]);
        qf[ks][2] = __float_as_uint(Qb[gid * 768 + ks * 8 + tig + 4]);
        qf[ks][3] = __float_as_uint(Qb[(gid + 8) * 768 + ks * 8 + tig + 4]);
    }

    float m0 = -1e30f, m1 = -1e30f, l0 = 0.f, l1 = 0.f;
    float oacc[4][4];
#pragma unroll
    for (int i = 0; i < 4; i++)
#pragma unroll
        for (int j = 0; j < 4; j++) oacc[i][j] = 0.f;

    // scale * log2(e):  (1/sqrt(32)) * 1.4426950408889634
    const float scale2 = 0.2550500337255891f;
    int kbmax = 2 * qb + 1;

    {
#pragma unroll
        for (int i = 0; i < 2; i++) {
            int idx = tid + 256 * i;
            int r = idx >> 3, c = (idx & 7) * 4;
            const float* p = qkv + (long long)(b * TT + r) * 768 + 256 + hh * 32 + c;
            cp_async16(kBase + (r * 36 + c) * 4, p);
            cp_async16(vBase + (r * 36 + c) * 4, p + 256);
        }
        cp_commit();
    }

    for (int kb = 0; kb <= kbmax; kb++) {
        int cur = kb & 1, nxt = cur ^ 1;
        cp_wait<0>();
        __syncthreads();
        if (kb < kbmax) {
#pragma unroll
            for (int i = 0; i < 2; i++) {
                int idx = tid + 256 * i;
                int r = idx >> 3, c = (idx & 7) * 4;
                const float* p = qkv + (long long)(b * TT + (kb + 1) * 64 + r) * 768 + 256 + hh * 32 + c;
                cp_async16(kBase + (nxt * KTILE + r * 36 + c) * 4, p);
                cp_async16(vBase + (nxt * KTILE + r * 36 + c) * 4, p + 256);
            }
        }
        cp_commit();

        if (kb * 64 > qrow + 15) continue;

        const float* Ks = KsB + cur * KTILE;
        const float* Vs = VsB + cur * KTILE;

        float sacc[8][4];
#pragma unroll
        for (int nt = 0; nt < 8; nt++)
#pragma unroll
            for (int c = 0; c < 4; c++) sacc[nt][c] = 0.f;
#pragma unroll
        for (int ks = 0; ks < 4; ks++) {
#pragma unroll
            for (int nt = 0; nt < 8; nt++) {
                unsigned bb[2];
                bb[0] = __float_as_uint(Ks[(nt * 8 + gid) * 36 + ks * 8 + tig]);
                bb[1] = __float_as_uint(Ks[(nt * 8 + gid) * 36 + ks * 8 + tig + 4]);
                mma_tf32(sacc[nt], qf[ks], bb);
            }
        }

        bool diag = (kb * 64 + 63 > qrow);
        int row0 = qrow + gid, row1 = row0 + 8;
        float rmax0 = -1e30f, rmax1 = -1e30f;
#pragma unroll
        for (int nt = 0; nt < 8; nt++) {
            int colb = kb * 64 + nt * 8 + tig * 2;
            float s0 = sacc[nt][0] * scale2;   // log2-domain scores
            float s1 = sacc[nt][1] * scale2;
            float s2 = sacc[nt][2] * scale2;
            float s3 = sacc[nt][3] * scale2;
            if (diag) {
                if (colb     > row0) s0 = -1e30f;
                if (colb + 1 > row0) s1 = -1e30f;
                if (colb     > row1) s2 = -1e30f;
                if (colb + 1 > row1) s3 = -1e30f;
            }
            sacc[nt][0] = s0; sacc[nt][1] = s1; sacc[nt][2] = s2; sacc[nt][3] = s3;
            rmax0 = fmaxf(rmax0, fmaxf(s0, s1));
            rmax1 = fmaxf(rmax1, fmaxf(s2, s3));
        }
        rmax0 = fmaxf(rmax0, __shfl_xor_sync(0xffffffffu, rmax0, 1));
        rmax0 = fmaxf(rmax0, __shfl_xor_sync(0xffffffffu, rmax0, 2));
        rmax1 = fmaxf(rmax1, __shfl_xor_sync(0xffffffffu, rmax1, 1));
        rmax1 = fmaxf(rmax1, __shfl_xor_sync(0xffffffffu, rmax1, 2));

        float newm0 = fmaxf(m0, rmax0), newm1 = fmaxf(m1, rmax1);
        float a0 = ex2(m0 - newm0), a1 = ex2(m1 - newm1);
        m0 = newm0; m1 = newm1;

        float ls0 = 0.f, ls1 = 0.f;
#pragma unroll
        for (int nt = 0; nt < 8; nt++) {
            float p0 = ex2(sacc[nt][0] - newm0);
            float p1 = ex2(sacc[nt][1] - newm0);
            float p2 = ex2(sacc[nt][2] - newm1);
            float p3 = ex2(sacc[nt][3] - newm1);
            ls0 += p0 + p1; ls1 += p2 + p3;
            Pw[gid * 68 + nt * 8 + tig * 2]           = p0;
            Pw[gid * 68 + nt * 8 + tig * 2 + 1]       = p1;
            Pw[(gid + 8) * 68 + nt * 8 + tig * 2]     = p2;
            Pw[(gid + 8) * 68 + nt * 8 + tig * 2 + 1] = p3;
        }
        ls0 += __shfl_xor_sync(0xffffffffu, ls0, 1);
        ls0 += __shfl_xor_sync(0xffffffffu, ls0, 2);
        ls1 += __shfl_xor_sync(0xffffffffu, ls1, 1);
        ls1 += __shfl_xor_sync(0xffffffffu, ls1, 2);
        l0 = l0 * a0 + ls0;
        l1 = l1 * a1 + ls1;
#pragma unroll
        for (int nt = 0; nt < 4; nt++) {
            oacc[nt][0] *= a0; oacc[nt][1] *= a0;
            oacc[nt][2] *= a1; oacc[nt][3] *= a1;
        }
        __syncwarp();

#pragma unroll
        for (int ks2 = 0; ks2 < 8; ks2++) {
            unsigned af[4];
            af[0] = __float_as_uint(Pw[gid * 68 + ks2 * 8 + tig]);
            af[1] = __float_as_uint(Pw[(gid + 8) * 68 + ks2 * 8 + tig]);
            af[2] = __float_as_uint(Pw[gid * 68 + ks2 * 8 + tig + 4]);
            af[3] = __float_as_uint(Pw[(gid + 8) * 68 + ks2 * 8 + tig + 4]);
#pragma unroll
            for (int nt2 = 0; nt2 < 4; nt2++) {
                unsigned bb[2];
                bb[0] = __float_as_uint(Vs[(ks2 * 8 + tig) * 36 + nt2 * 8 + gid]);
                bb[1] = __float_as_uint(Vs[(ks2 * 8 + tig + 4) * 36 + nt2 * 8 + gid]);
                mma_tf32(oacc[nt2], af, bb);
            }
        }
        __syncwarp();
    }

    float invl0 = 1.f / l0, invl1 = 1.f / l1;
#pragma unroll
    for (int nt2 = 0; nt2 < 4; nt2++) {
        int col = hh * 32 + nt2 * 8 + tig * 2;
        long long o0 = (long long)(b * TT + qrow + gid) * CC + col;
        long long o1 = (long long)(b * TT + qrow + gid + 8) * CC + col;
        *(float2*)&O[o0] = make_float2(f2tff(oacc[nt2][0] * invl0), f2tff(oacc[nt2][1] * invl0));
        *(float2*)&O[o1] = make_float2(f2tff(oacc[nt2][2] * invl1), f2tff(oacc[nt2][3] * invl1));
    }
}

// ============ fused spatial scores + softmax + head-mean ============
// qks pre-rounded to tf32 by producing GEMM -> raw loads, no cvt.
__global__ void __launch_bounds__(256)
spatial_sw(const float* __restrict__ qks, float* __restrict__ sw)
{
    int bid = blockIdx.x;
    int b = bid >> 4, ct = bid & 15;
    int c0 = ct * 16;
    int tid = threadIdx.x, warp = tid >> 5, lane = tid & 31;
    int gid = lane >> 2, tig = lane & 3;

    __shared__ float As[16][68];
    __shared__ float Bs[256][20];
    __shared__ float redA[8][17];
    __shared__ float redB[8][17];

    float macc[4][4];
#pragma unroll
    for (int i = 0; i < 4; i++)
#pragma unroll
        for (int j = 0; j < 4; j++) macc[i][j] = 0.f;

    // (1/sqrt(64)) * log2(e)
    const float scale2 = 0.18033688011112043f;

    for (int h = 0; h < 8; h++) {
        {
            int r = tid >> 4, c4 = tid & 15;
            float4 v = *(const float4*)&qks[(long long)(b * 256 + c0 + r) * 1024 + h * 64 + c4 * 4];
            *(float4*)&As[r][c4 * 4] = v;
        }

        float sacc[4][4];
#pragma unroll
        for (int i = 0; i < 4; i++)
#pragma unroll
            for (int j = 0; j < 4; j++) sacc[i][j] = 0.f;

        for (int kt = 0; kt < 4; kt++) {
#pragma unroll
            for (int i = 0; i < 4; i++) {
                int idx = tid + 256 * i;
                int e = idx >> 2, c4 = idx & 3;
                float4 v = *(const float4*)&qks[(long long)(b * 256 + e) * 1024 + 512 + h * 64 + kt * 16 + c4 * 4];
                *(float4*)&Bs[e][c4 * 4] = v;
            }
            __syncthreads();
#pragma unroll
            for (int ks = 0; ks < 2; ks++) {
                int kk = kt * 16 + ks * 8;
                unsigned af[4];
                af[0] = __float_as_uint(As[gid][kk + tig]);
                af[1] = __float_as_uint(As[gid + 8][kk + tig]);
                af[2] = __float_as_uint(As[gid][kk + tig + 4]);
                af[3] = __float_as_uint(As[gid + 8][kk + tig + 4]);
#pragma unroll
                for (int nt = 0; nt < 4; nt++) {
                    int n = warp * 32 + nt * 8 + gid;
                    unsigned bb[2];
                    bb[0] = __float_as_uint(Bs[n][ks * 8 + tig]);
                    bb[1] = __float_as_uint(Bs[n][ks * 8 + tig + 4]);
                    mma_tf32(sacc[nt], af, bb);
                }
            }
            __syncthreads();
        }

        float m0 = -1e30f, m1 = -1e30f;
#pragma unroll
        for (int nt = 0; nt < 4; nt++) {
            sacc[nt][0] *= scale2; sacc[nt][1] *= scale2;
            sacc[nt][2] *= scale2; sacc[nt][3] *= scale2;
            m0 = fmaxf(m0, fmaxf(sacc[nt][0], sacc[nt][1]));
            m1 = fmaxf(m1, fmaxf(sacc[nt][2], sacc[nt][3]));
        }
        m0 = fmaxf(m0, __shfl_xor_sync(0xffffffffu, m0, 1));
        m0 = fmaxf(m0, __shfl_xor_sync(0xffffffffu, m0, 2));
        m1 = fmaxf(m1, __shfl_xor_sync(0xffffffffu, m1, 1));
        m1 = fmaxf(m1, __shfl_xor_sync(0xffffffffu, m1, 2));
        if (tig == 0) { redA[warp][gid] = m0; redA[warp][gid + 8] = m1; }
        __syncthreads();
        float gm0 = -1e30f, gm1 = -1e30f;
#pragma unroll
        for (int w2 = 0; w2 < 8; w2++) {
            gm0 = fmaxf(gm0, redA[w2][gid]);
            gm1 = fmaxf(gm1, redA[w2][gid + 8]);
        }
        float ps0 = 0.f, ps1 = 0.f;
#pragma unroll
        for (int nt = 0; nt < 4; nt++) {
            sacc[nt][0] = ex2(sacc[nt][0] - gm0);
            sacc[nt][1] = ex2(sacc[nt][1] - gm0);
            sacc[nt][2] = ex2(sacc[nt][2] - gm1);
            sacc[nt][3] = ex2(sacc[nt][3] - gm1);
            ps0 += sacc[nt][0] + sacc[nt][1];
            ps1 += sacc[nt][2] + sacc[nt][3];
        }
        ps0 += __shfl_xor_sync(0xffffffffu, ps0, 1);
        ps0 += __shfl_xor_sync(0xffffffffu, ps0, 2);
        ps1 += __shfl_xor_sync(0xffffffffu, ps1, 1);
        ps1 += __shfl_xor_sync(0xffffffffu, ps1, 2);
        if (tig == 0) { redB[warp][gid] = ps0; redB[warp][gid + 8] = ps1; }
        __syncthreads();
        float gs0 = 0.f, gs1 = 0.f;
#pragma unroll
        for (int w2 = 0; w2 < 8; w2++) {
            gs0 += redB[w2][gid];
            gs1 += redB[w2][gid + 8];
        }
        float inv0 = 1.f / (8.f * gs0), inv1 = 1.f / (8.f * gs1);
#pragma unroll
        for (int nt = 0; nt < 4; nt++) {
            macc[nt][0] += sacc[nt][0] * inv0;
            macc[nt][1] += sacc[nt][1] * inv0;
            macc[nt][2] += sacc[nt][2] * inv1;
            macc[nt][3] += sacc[nt][3] * inv1;
        }
        __syncthreads();
    }

#pragma unroll
    for (int nt = 0; nt < 4; nt++) {
        int col = warp * 32 + nt * 8 + tig * 2;
        *(float2*)&sw[(long long)(b * 256 + c0 + gid) * 256 + col] =
            make_float2(macc[nt][0], macc[nt][1]);
        *(float2*)&sw[(long long)(b * 256 + c0 + gid + 8) * 256 + col] =
            make_float2(macc[nt][2], macc[nt][3]);
    }
}

// ---------------- host launch ----------------
// mode: 0 = <0,0,0>, 1 = <0,0,1>, 2 = <1,1,0>
static void gemm(const float* A, const float* Bw, const float* bias, const float* res, float* C,
                 int M, int N, int K, int lda, int ldb, int ldc,
                 int nbatch, int nb2,
                 long long sA1, long long sA2, long long sB1, long long sB2,
                 long long sC1, long long sC2, int relu, int mode)
{
    dim3 grid(N / BN, M / BM, nbatch);
    if (mode == 1)
        gemm_tc<0,0,1><<<grid, 256, GEMM_SMEM>>>(A, Bw, bias, res, C, M, N, K, lda, ldb, ldc,
                                                 nb2, sA1, sA2, sB1, sB2, sC1, sC2, relu);
    else if (mode == 2)
        gemm_tc<1,1,0><<<grid, 256, GEMM_SMEM>>>(A, Bw, bias, res, C, M, N, K, lda, ldb, ldc,
                                                 nb2, sA1, sA2, sB1, sB2, sC1, sC2, relu);
    else
        gemm_tc<0,0,0><<<grid, 256, GEMM_SMEM>>>(A, Bw, bias, res, C, M, N, K, lda, ldb, ldc,
                                                 nb2, sA1, sA2, sB1, sB2, sC1, sC2, relu);
}

extern "C" void kernel_launch(void* const* d_in, const int* in_sizes, int n_in,
                              void* d_out, int out_size)
{
    const float* x_T     = (const float*)d_in[0];
    const float* x_S     = (const float*)d_in[1];
    const float* Wq_t    = (const float*)d_in[2];
    const float* Wk_t    = (const float*)d_in[3];
    const float* Wv_t    = (const float*)d_in[4];
    const float* Wo      = (const float*)d_in[5];
    const float* Wq_s    = (const float*)d_in[6];
    const float* Wk_s    = (const float*)d_in[7];
    const float* ff1_w1  = (const float*)d_in[8];
    const float* ff1_b1  = (const float*)d_in[9];
    const float* ff1_w2  = (const float*)d_in[10];
    const float* ff1_b2  = (const float*)d_in[11];
    const float* ff2_w1  = (const float*)d_in[12];
    const float* ff2_b1  = (const float*)d_in[13];
    const float* ff2_w2  = (const float*)d_in[14];
    const float* ff2_b2  = (const float*)d_in[15];
    const float* t_ln1_w = (const float*)d_in[16];
    const float* t_ln1_b = (const float*)d_in[17];
    const float* t_ln2_w = (const float*)d_in[18];
    const float* t_ln2_b = (const float*)d_in[19];
    const float* s_ln1_w = (const float*)d_in[20];
    const float* s_ln1_b = (const float*)d_in[21];
    const float* fus_ln_w= (const float*)d_in[22];
    const float* fus_ln_b= (const float*)d_in[23];

    float *h, *qkv, *o, *x, *u, *to, *hs, *qks, *x2;
    float *wqkv, *wqks, *wo, *w11, *w12, *w21, *w22;
    cudaGetSymbolAddress((void**)&h,    g_h);
    cudaGetSymbolAddress((void**)&qkv,  g_qkv);
    cudaGetSymbolAddress((void**)&o,    g_o);
    cudaGetSymbolAddress((void**)&x,    g_x);
    cudaGetSymbolAddress((void**)&u,    g_u);
    cudaGetSymbolAddress((void**)&to,   g_to);
    cudaGetSymbolAddress((void**)&hs,   g_hs);
    cudaGetSymbolAddress((void**)&qks,  g_qks);
    cudaGetSymbolAddress((void**)&x2,   g_x2);
    cudaGetSymbolAddress((void**)&wqkv, g_wqkv);
    cudaGetSymbolAddress((void**)&wqks, g_wqks);
    cudaGetSymbolAddress((void**)&wo,   g_wo);
    cudaGetSymbolAddress((void**)&w11,  g_w11);
    cudaGetSymbolAddress((void**)&w12,  g_w12);
    cudaGetSymbolAddress((void**)&w21,  g_w21);
    cudaGetSymbolAddress((void**)&w22,  g_w22);

    float* out = (float*)d_out;                 // [B,T,C]
    float* sw  = out + (long long)ROWS_T * CC;  // spatial_weights [B,C,C]

    cudaFuncSetAttribute(gemm_tc<0,0,0>, cudaFuncAttributeMaxDynamicSharedMemorySize, GEMM_SMEM);
    cudaFuncSetAttribute(gemm_tc<0,0,1>, cudaFuncAttributeMaxDynamicSharedMemorySize, GEMM_SMEM);
    cudaFuncSetAttribute(gemm_tc<1,1,0>, cudaFuncAttributeMaxDynamicSharedMemorySize, GEMM_SMEM);
    cudaFuncSetAttribute(attn_tc, cudaFuncAttributeMaxDynamicSharedMemorySize, ATTN_SMEM);

    // pack + pre-round weights (one node)
    pack_weights<<<262144/256, 256>>>(Wq_t, Wk_t, Wv_t, Wo, Wq_s, Wk_s,
                                      ff1_w1, ff1_w2, ff2_w1, ff2_w2,
                                      wqkv, wqks, wo, w11, w12, w21, w22);

    // ---- temporal branch ----
    ln_warp<2><<<ROWS_T/8, 256>>>(x_T, t_ln1_w, t_ln1_b, h);
    gemm(h, wqkv, 0, 0, qkv, ROWS_T, 768, CC, CC, CC, 768, 1,1, 0,0,0,0,0,0, 0, 1);
    attn_tc<<<dim3(TT/128, BB*HH), 256, ATTN_SMEM>>>(qkv, o);
    gemm(o, wo, 0, x_T, x, ROWS_T, CC, CC, CC, CC, CC, 1,1, 0,0,0,0,0,0, 0, 0);
    ln_warp<2><<<ROWS_T/8, 256>>>(x, t_ln2_w, t_ln2_b, h);
    gemm(h, w11, ff1_b1, 0, u,  ROWS_T, 4*CC, CC, CC, CC, 4*CC, 1,1, 0,0,0,0,0,0, 1, 1);
    gemm(u, w12, ff1_b2, x, to, ROWS_T, CC, 4*CC, 4*CC, 4*CC, CC, 1,1, 0,0,0,0,0,0, 0, 0);

    // ---- spatial branch ----
    ln_warp<4><<<ROWS_S/8, 256>>>(x_S, s_ln1_w, s_ln1_b, hs);
    gemm(hs, wqks, 0, 0, qks, ROWS_S, 1024, TT, TT, TT, 1024, 1,1, 0,0,0,0,0,0, 0, 1);
    spatial_sw<<<256, 256>>>(qks, sw);

    // ---- fusion: x2 = TO + TO @ sw^T (batched over b; to/sw need cvt) ----
    gemm(to, sw, 0, to, x2, TT, CC, CC, CC, CC, CC,
         BB, 1,
         (long long)TT*CC, 0, (long long)CC*CC, 0, (long long)TT*CC, 0, 0, 2);

    // ---- FFN2 -> out ----
    ln_warp<2><<<ROWS_T/8, 256>>>(x2, fus_ln_w, fus_ln_b, h);
    gemm(h, w21, ff2_b1, 0, u, ROWS_T, 4*CC, CC, CC, CC, 4*CC, 1,1, 0,0,0,0,0,0, 1, 1);
    gemm(u, w22, ff2_b2, x2, out, ROWS_T, CC, 4*CC, 4*CC, 4*CC, CC, 1,1, 0,0,0,0,0,0, 0, 0);
}

// round 17
// speedup vs baseline: 1.0585x; 1.0121x over previous
#include <cuda_runtime.h>
#include <math.h>

// Problem constants
#define BB 16
#define TT 512
#define CC 256
#define HH 8
#define ROWS_T (BB*TT)      // 8192
#define ROWS_S (BB*CC)      // 4096

// ---------------- scratch (device globals; no allocation allowed) ----------------
__device__ float g_h[ROWS_T*CC];
__device__ float g_qkv[ROWS_T*3*CC];
__device__ float g_o[ROWS_T*CC];
__device__ float g_x[ROWS_T*CC];
__device__ float g_u[ROWS_T*4*CC];
__device__ float g_to[ROWS_T*CC];
__device__ float g_hs[ROWS_S*TT];
__device__ float g_qks[ROWS_S*2*512];
__device__ float g_x2[ROWS_T*CC];
__device__ float g_wqkv[768*256];     // packed + tf32-rounded
__device__ float g_wqks[1024*512];    // packed + tf32-rounded
__device__ float g_wo[256*256];
__device__ float g_w11[1024*256];
__device__ float g_w12[256*1024];
__device__ float g_w21[1024*256];
__device__ float g_w22[256*1024];

__device__ __forceinline__ unsigned f2tf(float f) {
    unsigned u;
    asm("cvt.rna.tf32.f32 %0, %1;" : "=r"(u) : "f"(f));
    return u;
}
__device__ __forceinline__ float f2tff(float f) { return __uint_as_float(f2tf(f)); }

__device__ __forceinline__ float ex2(float x) {
    float y;
    asm("ex2.approx.f32 %0, %1;" : "=f"(y) : "f"(x));
    return y;
}

__device__ __forceinline__ void mma_tf32(float d[4], const unsigned a[4], const unsigned b[2]) {
    asm("mma.sync.aligned.m16n8k8.row.col.f32.tf32.tf32.f32 "
        "{%0,%1,%2,%3}, {%4,%5,%6,%7}, {%8,%9}, {%0,%1,%2,%3};"
        : "+f"(d[0]), "+f"(d[1]), "+f"(d[2]), "+f"(d[3])
        : "r"(a[0]), "r"(a[1]), "r"(a[2]), "r"(a[3]), "r"(b[0]), "r"(b[1]));
}

__device__ __forceinline__ void cp_async16(unsigned smem_addr, const void* gptr) {
    asm volatile("cp.async.cg.shared.global [%0], [%1], 16;" :: "r"(smem_addr), "l"(gptr));
}
__device__ __forceinline__ void cp_commit() {
    asm volatile("cp.async.commit_group;");
}
template<int N>
__device__ __forceinline__ void cp_wait() {
    asm volatile("cp.async.wait_group %0;" :: "n"(N));
}

// ===== tf32 tensor-core GEMM, cp.async 3-stage pipeline, BK=32:  C = A @ B^T ====
// ACVT/BCVT: whether A/B need tf32 rounding on fragment read (0 = pre-rounded).
// CRND: round C to tf32 on store (for consumers that read C as a GEMM/MMA input).
#define BM 128
#define BN 128
#define BK 32
#define TSTR 36
#define STG_F (128 * TSTR)
#define GEMM_SMEM (3 * 2 * STG_F * 4)   // 110592 bytes

template<int ACVT, int BCVT, int CRND>
__global__ void __launch_bounds__(256, 2)
gemm_tc(const float* __restrict__ A, const float* __restrict__ Bw,
        const float* __restrict__ bias, const float* __restrict__ res,
        float* __restrict__ C,
        int M, int N, int K, int lda, int ldb, int ldc,
        int nb2,
        long long sA1, long long sA2, long long sB1, long long sB2,
        long long sC1, long long sC2, int relu)
{
    extern __shared__ float smg[];
    float* Asm = smg;
    float* Bsm = smg + 3 * STG_F;

    int z = blockIdx.z;
    int b1 = z / nb2, b2 = z - b1 * nb2;
    A  += (long long)b1 * sA1 + (long long)b2 * sA2;
    Bw += (long long)b1 * sB1 + (long long)b2 * sB2;
    long long co = (long long)b1 * sC1 + (long long)b2 * sC2;
    C += co;
    if (res) res += co;

    int tid = threadIdx.x;
    int warp = tid >> 5, lane = tid & 31;
    int wm = warp >> 2;
    int wn = warp & 3;
    int gid = lane >> 2, tig = lane & 3;
    int bm = blockIdx.y * BM, bn = blockIdx.x * BN;

    unsigned aBase = (unsigned)__cvta_generic_to_shared(Asm);
    unsigned bBase = (unsigned)__cvta_generic_to_shared(Bsm);

    float acc[4][4][4];
#pragma unroll
    for (int i = 0; i < 4; i++)
#pragma unroll
        for (int j = 0; j < 4; j++)
#pragma unroll
            for (int l = 0; l < 4; l++) acc[i][j][l] = 0.f;

    int nk = K / BK;

#pragma unroll
    for (int s = 0; s < 2; s++) {
        if (s < nk) {
            int k0 = s * BK;
#pragma unroll
            for (int i = 0; i < 4; i++) {
                int idx = tid + 256 * i;
                int r = idx >> 3, c = (idx & 7) * 4;
                cp_async16(aBase + (s * STG_F + r * TSTR + c) * 4,
                           &A[(long long)(bm + r) * lda + k0 + c]);
                cp_async16(bBase + (s * STG_F + r * TSTR + c) * 4,
                           &Bw[(long long)(bn + r) * ldb + k0 + c]);
            }
        }
        cp_commit();
    }
    cp_wait<1>();
    __syncthreads();

    for (int kt = 0; kt < nk; kt++) {
        int cur = kt % 3;
        {
            int sst = (kt + 2) % 3;
            if (kt + 2 < nk) {
                int k0 = (kt + 2) * BK;
#pragma unroll
                for (int i = 0; i < 4; i++) {
                    int idx = tid + 256 * i;
                    int r = idx >> 3, c = (idx & 7) * 4;
                    cp_async16(aBase + (sst * STG_F + r * TSTR + c) * 4,
                               &A[(long long)(bm + r) * lda + k0 + c]);
                    cp_async16(bBase + (sst * STG_F + r * TSTR + c) * 4,
                               &Bw[(long long)(bn + r) * ldb + k0 + c]);
                }
            }
            cp_commit();
        }

        const float* Ac = Asm + cur * STG_F;
        const float* Bc = Bsm + cur * STG_F;
#pragma unroll
        for (int ks = 0; ks < 4; ks++) {
            unsigned af[4][4], bf[4][2];
            int kk = ks * 8;
#pragma unroll
            for (int mt = 0; mt < 4; mt++) {
                int r = wm * 64 + mt * 16 + gid;
                if (ACVT) {
                    af[mt][0] = f2tf(Ac[r * TSTR + kk + tig]);
                    af[mt][1] = f2tf(Ac[(r + 8) * TSTR + kk + tig]);
                    af[mt][2] = f2tf(Ac[r * TSTR + kk + tig + 4]);
                    af[mt][3] = f2tf(Ac[(r + 8) * TSTR + kk + tig + 4]);
                } else {
                    af[mt][0] = __float_as_uint(Ac[r * TSTR + kk + tig]);
                    af[mt][1] = __float_as_uint(Ac[(r + 8) * TSTR + kk + tig]);
                    af[mt][2] = __float_as_uint(Ac[r * TSTR + kk + tig + 4]);
                    af[mt][3] = __float_as_uint(Ac[(r + 8) * TSTR + kk + tig + 4]);
                }
            }
#pragma unroll
            for (int nt = 0; nt < 4; nt++) {
                int n = wn * 32 + nt * 8 + gid;
                if (BCVT) {
                    bf[nt][0] = f2tf(Bc[n * TSTR + kk + tig]);
                    bf[nt][1] = f2tf(Bc[n * TSTR + kk + tig + 4]);
                } else {
                    bf[nt][0] = __float_as_uint(Bc[n * TSTR + kk + tig]);
                    bf[nt][1] = __float_as_uint(Bc[n * TSTR + kk + tig + 4]);
                }
            }
#pragma unroll
            for (int mt = 0; mt < 4; mt++)
#pragma unroll
                for (int nt = 0; nt < 4; nt++)
                    mma_tf32(acc[mt][nt], af[mt], bf[nt]);
        }

        cp_wait<1>();
        __syncthreads();
    }

#pragma unroll
    for (int mt = 0; mt < 4; mt++) {
        int row = bm + wm * 64 + mt * 16 + gid;
#pragma unroll
        for (int nt = 0; nt < 4; nt++) {
            int col = bn + wn * 32 + nt * 8 + tig * 2;
            float v0 = acc[mt][nt][0], v1 = acc[mt][nt][1];
            float v2 = acc[mt][nt][2], v3 = acc[mt][nt][3];
            if (bias) {
                float b0 = bias[col], b1 = bias[col + 1];
                v0 += b0; v1 += b1; v2 += b0; v3 += b1;
            }
            if (res) {
                const float2 r0 = *(const float2*)&res[(long long)row * ldc + col];
                const float2 r1 = *(const float2*)&res[(long long)(row + 8) * ldc + col];
                v0 += r0.x; v1 += r0.y; v2 += r1.x; v3 += r1.y;
            }
            if (relu) {
                v0 = fmaxf(v0, 0.f); v1 = fmaxf(v1, 0.f);
                v2 = fmaxf(v2, 0.f); v3 = fmaxf(v3, 0.f);
            }
            if (CRND) {
                v0 = f2tff(v0); v1 = f2tff(v1);
                v2 = f2tff(v2); v3 = f2tff(v3);
            }
            *(float2*)&C[(long long)row * ldc + col] = make_float2(v0, v1);
            *(float2*)&C[(long long)(row + 8) * ldc + col] = make_float2(v2, v3);
        }
    }
}

// ---------------- weight pack + tf32 pre-round ----------------
__global__ void pack_weights(const float* __restrict__ Wq, const float* __restrict__ Wk,
                             const float* __restrict__ Wv, const float* __restrict__ Wo,
                             const float* __restrict__ Wqs, const float* __restrict__ Wks,
                             const float* __restrict__ w11, const float* __restrict__ w12,
                             const float* __restrict__ w21, const float* __restrict__ w22,
                             float* __restrict__ wqkv, float* __restrict__ wqks,
                             float* __restrict__ owo, float* __restrict__ o11,
                             float* __restrict__ o12, float* __restrict__ o21,
                             float* __restrict__ o22)
{
    int i = blockIdx.x * 256 + threadIdx.x;   // grid covers 262144
    if (i < 65536) {
        wqkv[i]          = f2tff(Wq[i]);
        wqkv[i + 65536]  = f2tff(Wk[i]);
        wqkv[i + 131072] = f2tff(Wv[i]);
        owo[i]           = f2tff(Wo[i]);
    }
    wqks[i]          = f2tff(Wqs[i]);
    wqks[i + 262144] = f2tff(Wks[i]);
    o11[i] = f2tff(w11[i]);
    o12[i] = f2tff(w12[i]);
    o21[i] = f2tff(w21[i]);
    o22[i] = f2tff(w22[i]);
}

// ---------------- LayerNorm: warp per row, tf32-rounded output ----------------
template<int F4>
__global__ void __launch_bounds__(256)
ln_warp(const float* __restrict__ x, const float* __restrict__ w,
        const float* __restrict__ bp, float* __restrict__ y)
{
    const int D = F4 * 128;
    int warp = threadIdx.x >> 5, lane = threadIdx.x & 31;
    long long row = (long long)blockIdx.x * 8 + warp;
    const float* xr = x + row * D;
    float* yr = y + row * D;

    float4 v[F4];
    float s = 0.f, sq = 0.f;
#pragma unroll
    for (int i = 0; i < F4; i++) {
        v[i] = *(const float4*)&xr[lane * 4 + i * 128];
        s  += v[i].x + v[i].y + v[i].z + v[i].w;
        sq += v[i].x*v[i].x + v[i].y*v[i].y + v[i].z*v[i].z + v[i].w*v[i].w;
    }
#pragma unroll
    for (int off = 16; off; off >>= 1) {
        s  += __shfl_xor_sync(0xffffffffu, s, off);
        sq += __shfl_xor_sync(0xffffffffu, sq, off);
    }
    float mean = s / D;
    float var = sq / D - mean * mean;
    float inv = rsqrtf(var + 1e-6f);
#pragma unroll
    for (int i = 0; i < F4; i++) {
        int c = lane * 4 + i * 128;
        float4 wv = *(const float4*)&w[c];
        float4 bv = *(const float4*)&bp[c];
        float4 r;
        r.x = f2tff((v[i].x - mean) * inv * wv.x + bv.x);
        r.y = f2tff((v[i].y - mean) * inv * wv.y + bv.y);
        r.z = f2tff((v[i].z - mean) * inv * wv.z + bv.z);
        r.w = f2tff((v[i].w - mean) * inv * wv.w + bv.w);
        *(float4*)&yr[c] = r;
    }
}

// ============ tensor-core causal flash attention (D=32), cp.async K/V ===========
// 4 warps / 64 q-rows per block, grid (8, B*H) = 1024 blocks. kbmax = qb,
// so every warp is active on every K-tile (100% causal utilization).
// qkv pre-rounded to tf32 by producing GEMM. Softmax in exp2 domain.
#define KTILE (64*36)
#define ATTN_SMEM ((4*KTILE + 4*16*68) * 4)   // 54272 bytes
__global__ void __launch_bounds__(128)
attn_tc(const float* __restrict__ qkv, float* __restrict__ O)
{
    extern __shared__ float sm[];
    float* KsB = sm;
    float* VsB = sm + 2 * KTILE;
    int qb = gridDim.x - 1 - blockIdx.x;   // heaviest blocks first
    int bh = blockIdx.y;
    int b = bh >> 3, hh = bh & 7;
    int tid = threadIdx.x, warp = tid >> 5, lane = tid & 31;
    int gid = lane >> 2, tig = lane & 3;
    float* Pw = sm + 4 * KTILE + warp * 16 * 68;

    unsigned kBase = (unsigned)__cvta_generic_to_shared(KsB);
    unsigned vBase = (unsigned)__cvta_generic_to_shared(VsB);

    int qrow = qb * 64 + warp * 16;
    const float* Qb = qkv + (long long)(b * TT + qrow) * 768 + hh * 32;

    unsigned qf[4][4];
#pragma unroll
    for (int ks = 0; ks < 4; ks++) {
        qf[ks][0] = __float_as_uint(Qb[gid * 768 + ks * 8 + tig]);
        qf[ks][1] = __float_as_uint(Qb[(gid + 8) * 768 + ks * 8 + tig]);
        qf[ks][2] = __float_as_uint(Qb[gid * 768 + ks * 8 + tig + 4]);
        qf[ks][3] = __float_as_uint(Qb[(gid + 8) * 768 + ks * 8 + tig + 4]);
    }

    float m0 = -1e30f, m1 = -1e30f, l0 = 0.f, l1 = 0.f;
    float oacc[4][4];
#pragma unroll
    for (int i = 0; i < 4; i++)
#pragma unroll
        for (int j = 0; j < 4; j++) oacc[i][j] = 0.f;

    // scale * log2(e):  (1/sqrt(32)) * 1.4426950408889634
    const float scale2 = 0.2550500337255891f;
    int kbmax = qb;

    {
#pragma unroll
        for (int i = 0; i < 4; i++) {
            int idx = tid + 128 * i;        // 512 float4 slots per tile
            int r = idx >> 3, c = (idx & 7) * 4;
            const float* p = qkv + (long long)(b * TT + r) * 768 + 256 + hh * 32 + c;
            cp_async16(kBase + (r * 36 + c) * 4, p);
            cp_async16(vBase + (r * 36 + c) * 4, p + 256);
        }
        cp_commit();
    }

    for (int kb = 0; kb <= kbmax; kb++) {
        int cur = kb & 1, nxt = cur ^ 1;
        cp_wait<0>();
        __syncthreads();
        if (kb < kbmax) {
#pragma unroll
            for (int i = 0; i < 4; i++) {
                int idx = tid + 128 * i;
                int r = idx >> 3, c = (idx & 7) * 4;
                const float* p = qkv + (long long)(b * TT + (kb + 1) * 64 + r) * 768 + 256 + hh * 32 + c;
                cp_async16(kBase + (nxt * KTILE + r * 36 + c) * 4, p);
                cp_async16(vBase + (nxt * KTILE + r * 36 + c) * 4, p + 256);
            }
        }
        cp_commit();

        const float* Ks = KsB + cur * KTILE;
        const float* Vs = VsB + cur * KTILE;

        float sacc[8][4];
#pragma unroll
        for (int nt = 0; nt < 8; nt++)
#pragma unroll
            for (int c = 0; c < 4; c++) sacc[nt][c] = 0.f;
#pragma unroll
        for (int ks = 0; ks < 4; ks++) {
#pragma unroll
            for (int nt = 0; nt < 8; nt++) {
                unsigned bb[2];
                bb[0] = __float_as_uint(Ks[(nt * 8 + gid) * 36 + ks * 8 + tig]);
                bb[1] = __float_as_uint(Ks[(nt * 8 + gid) * 36 + ks * 8 + tig + 4]);
                mma_tf32(sacc[nt], qf[ks], bb);
            }
        }

        bool diag = (kb == kbmax);
        int row0 = qrow + gid, row1 = row0 + 8;
        float rmax0 = -1e30f, rmax1 = -1e30f;
#pragma unroll
        for (int nt = 0; nt < 8; nt++) {
            int colb = kb * 64 + nt * 8 + tig * 2;
            float s0 = sacc[nt][0] * scale2;   // log2-domain scores
            float s1 = sacc[nt][1] * scale2;
            float s2 = sacc[nt][2] * scale2;
            float s3 = sacc[nt][3] * scale2;
            if (diag) {
                if (colb     > row0) s0 = -1e30f;
                if (colb + 1 > row0) s1 = -1e30f;
                if (colb     > row1) s2 = -1e30f;
                if (colb + 1 > row1) s3 = -1e30f;
            }
            sacc[nt][0] = s0; sacc[nt][1] = s1; sacc[nt][2] = s2; sacc[nt][3] = s3;
            rmax0 = fmaxf(rmax0, fmaxf(s0, s1));
            rmax1 = fmaxf(rmax1, fmaxf(s2, s3));
        }
        rmax0 = fmaxf(rmax0, __shfl_xor_sync(0xffffffffu, rmax0, 1));
        rmax0 = fmaxf(rmax0, __shfl_xor_sync(0xffffffffu, rmax0, 2));
        rmax1 = fmaxf(rmax1, __shfl_xor_sync(0xffffffffu, rmax1, 1));
        rmax1 = fmaxf(rmax1, __shfl_xor_sync(0xffffffffu, rmax1, 2));

        float newm0 = fmaxf(m0, rmax0), newm1 = fmaxf(m1, rmax1);
        float a0 = ex2(m0 - newm0), a1 = ex2(m1 - newm1);
        m0 = newm0; m1 = newm1;

        float ls0 = 0.f, ls1 = 0.f;
#pragma unroll
        for (int nt = 0; nt < 8; nt++) {
            float p0 = ex2(sacc[nt][0] - newm0);
            float p1 = ex2(sacc[nt][1] - newm0);
            float p2 = ex2(sacc[nt][2] - newm1);
            float p3 = ex2(sacc[nt][3] - newm1);
            ls0 += p0 + p1; ls1 += p2 + p3;
            Pw[gid * 68 + nt * 8 + tig * 2]           = p0;
            Pw[gid * 68 + nt * 8 + tig * 2 + 1]       = p1;
            Pw[(gid + 8) * 68 + nt * 8 + tig * 2]     = p2;
            Pw[(gid + 8) * 68 + nt * 8 + tig * 2 + 1] = p3;
        }
        ls0 += __shfl_xor_sync(0xffffffffu, ls0, 1);
        ls0 += __shfl_xor_sync(0xffffffffu, ls0, 2);
        ls1 += __shfl_xor_sync(0xffffffffu, ls1, 1);
        ls1 += __shfl_xor_sync(0xffffffffu, ls1, 2);
        l0 = l0 * a0 + ls0;
        l1 = l1 * a1 + ls1;
#pragma unroll
        for (int nt = 0; nt < 4; nt++) {
            oacc[nt][0] *= a0; oacc[nt][1] *= a0;
            oacc[nt][2] *= a1; oacc[nt][3] *= a1;
        }
        __syncwarp();

#pragma unroll
        for (int ks2 = 0; ks2 < 8; ks2++) {
            unsigned af[4];
            af[0] = __float_as_uint(Pw[gid * 68 + ks2 * 8 + tig]);
            af[1] = __float_as_uint(Pw[(gid + 8) * 68 + ks2 * 8 + tig]);
            af[2] = __float_as_uint(Pw[gid * 68 + ks2 * 8 + tig + 4]);
            af[3] = __float_as_uint(Pw[(gid + 8) * 68 + ks2 * 8 + tig + 4]);
#pragma unroll
            for (int nt2 = 0; nt2 < 4; nt2++) {
                unsigned bb[2];
                bb[0] = __float_as_uint(Vs[(ks2 * 8 + tig) * 36 + nt2 * 8 + gid]);
                bb[1] = __float_as_uint(Vs[(ks2 * 8 + tig + 4) * 36 + nt2 * 8 + gid]);
                mma_tf32(oacc[nt2], af, bb);
            }
        }
        __syncwarp();
    }

    float invl0 = 1.f / l0, invl1 = 1.f / l1;
#pragma unroll
    for (int nt2 = 0; nt2 < 4; nt2++) {
        int col = hh * 32 + nt2 * 8 + tig * 2;
        long long o0 = (long long)(b * TT + qrow + gid) * CC + col;
        long long o1 = (long long)(b * TT + qrow + gid + 8) * CC + col;
        *(float2*)&O[o0] = make_float2(f2tff(oacc[nt2][0] * invl0), f2tff(oacc[nt2][1] * invl0));
        *(float2*)&O[o1] = make_float2(f2tff(oacc[nt2][2] * invl1), f2tff(oacc[nt2][3] * invl1));
    }
}

// ============ fused spatial scores + softmax + head-mean ============
// qks pre-rounded to tf32 by producing GEMM -> raw loads, no cvt.
__global__ void __launch_bounds__(256)
spatial_sw(const float* __restrict__ qks, float* __restrict__ sw)
{
    int bid = blockIdx.x;
    int b = bid >> 4, ct = bid & 15;
    int c0 = ct * 16;
    int tid = threadIdx.x, warp = tid >> 5, lane = tid & 31;
    int gid = lane >> 2, tig = lane & 3;

    __shared__ float As[16][68];
    __shared__ float Bs[256][20];
    __shared__ float redA[8][17];
    __shared__ float redB[8][17];

    float macc[4][4];
#pragma unroll
    for (int i = 0; i < 4; i++)
#pragma unroll
        for (int j = 0; j < 4; j++) macc[i][j] = 0.f;

    // (1/sqrt(64)) * log2(e)
    const float scale2 = 0.18033688011112043f;

    for (int h = 0; h < 8; h++) {
        {
            int r = tid >> 4, c4 = tid & 15;
            float4 v = *(const float4*)&qks[(long long)(b * 256 + c0 + r) * 1024 + h * 64 + c4 * 4];
            *(float4*)&As[r][c4 * 4] = v;
        }

        float sacc[4][4];
#pragma unroll
        for (int i = 0; i < 4; i++)
#pragma unroll
            for (int j = 0; j < 4; j++) sacc[i][j] = 0.f;

        for (int kt = 0; kt < 4; kt++) {
#pragma unroll
            for (int i = 0; i < 4; i++) {
                int idx = tid + 256 * i;
                int e = idx >> 2, c4 = idx & 3;
                float4 v = *(const float4*)&qks[(long long)(b * 256 + e) * 1024 + 512 + h * 64 + kt * 16 + c4 * 4];
                *(float4*)&Bs[e][c4 * 4] = v;
            }
            __syncthreads();
#pragma unroll
            for (int ks = 0; ks < 2; ks++) {
                int kk = kt * 16 + ks * 8;
                unsigned af[4];
                af[0] = __float_as_uint(As[gid][kk + tig]);
                af[1] = __float_as_uint(As[gid + 8][kk + tig]);
                af[2] = __float_as_uint(As[gid][kk + tig + 4]);
                af[3] = __float_as_uint(As[gid + 8][kk + tig + 4]);
#pragma unroll
                for (int nt = 0; nt < 4; nt++) {
                    int n = warp * 32 + nt * 8 + gid;
                    unsigned bb[2];
                    bb[0] = __float_as_uint(Bs[n][ks * 8 + tig]);
                    bb[1] = __float_as_uint(Bs[n][ks * 8 + tig + 4]);
                    mma_tf32(sacc[nt], af, bb);
                }
            }
            __syncthreads();
        }

        float m0 = -1e30f, m1 = -1e30f;
#pragma unroll
        for (int nt = 0; nt < 4; nt++) {
            sacc[nt][0] *= scale2; sacc[nt][1] *= scale2;
            sacc[nt][2] *= scale2; sacc[nt][3] *= scale2;
            m0 = fmaxf(m0, fmaxf(sacc[nt][0], sacc[nt][1]));
            m1 = fmaxf(m1, fmaxf(sacc[nt][2], sacc[nt][3]));
        }
        m0 = fmaxf(m0, __shfl_xor_sync(0xffffffffu, m0, 1));
        m0 = fmaxf(m0, __shfl_xor_sync(0xffffffffu, m0, 2));
        m1 = fmaxf(m1, __shfl_xor_sync(0xffffffffu, m1, 1));
        m1 = fmaxf(m1, __shfl_xor_sync(0xffffffffu, m1, 2));
        if (tig == 0) { redA[warp][gid] = m0; redA[warp][gid + 8] = m1; }
        __syncthreads();
        float gm0 = -1e30f, gm1 = -1e30f;
#pragma unroll
        for (int w2 = 0; w2 < 8; w2++) {
            gm0 = fmaxf(gm0, redA[w2][gid]);
            gm1 = fmaxf(gm1, redA[w2][gid + 8]);
        }
        float ps0 = 0.f, ps1 = 0.f;
#pragma unroll
        for (int nt = 0; nt < 4; nt++) {
            sacc[nt][0] = ex2(sacc[nt][0] - gm0);
            sacc[nt][1] = ex2(sacc[nt][1] - gm0);
            sacc[nt][2] = ex2(sacc[nt][2] - gm1);
            sacc[nt][3] = ex2(sacc[nt][3] - gm1);
            ps0 += sacc[nt][0] + sacc[nt][1];
            ps1 += sacc[nt][2] + sacc[nt][3];
        }
        ps0 += __shfl_xor_sync(0xffffffffu, ps0, 1);
        ps0 += __shfl_xor_sync(0xffffffffu, ps0, 2);
        ps1 += __shfl_xor_sync(0xffffffffu, ps1, 1);
        ps1 += __shfl_xor_sync(0xffffffffu, ps1, 2);
        if (tig == 0) { redB[warp][gid] = ps0; redB[warp][gid + 8] = ps1; }
        __syncthreads();
        float gs0 = 0.f, gs1 = 0.f;
#pragma unroll
        for (int w2 = 0; w2 < 8; w2++) {
            gs0 += redB[w2][gid];
            gs1 += redB[w2][gid + 8];
        }
        float inv0 = 1.f / (8.f * gs0), inv1 = 1.f / (8.f * gs1);
#pragma unroll
        for (int nt = 0; nt < 4; nt++) {
            macc[nt][0] += sacc[nt][0] * inv0;
            macc[nt][1] += sacc[nt][1] * inv0;
            macc[nt][2] += sacc[nt][2] * inv1;
            macc[nt][3] += sacc[nt][3] * inv1;
        }
        __syncthreads();
    }

#pragma unroll
    for (int nt = 0; nt < 4; nt++) {
        int col = warp * 32 + nt * 8 + tig * 2;
        *(float2*)&sw[(long long)(b * 256 + c0 + gid) * 256 + col] =
            make_float2(macc[nt][0], macc[nt][1]);
        *(float2*)&sw[(long long)(b * 256 + c0 + gid + 8) * 256 + col] =
            make_float2(macc[nt][2], macc[nt][3]);
    }
}

// ---------------- host launch ----------------
// mode: 0 = <0,0,0>, 1 = <0,0,1>, 2 = <1,1,0>
static void gemm(const float* A, const float* Bw, const float* bias, const float* res, float* C,
                 int M, int N, int K, int lda, int ldb, int ldc,
                 int nbatch, int nb2,
                 long long sA1, long long sA2, long long sB1, long long sB2,
                 long long sC1, long long sC2, int relu, int mode)
{
    dim3 grid(N / BN, M / BM, nbatch);
    if (mode == 1)
        gemm_tc<0,0,1><<<grid, 256, GEMM_SMEM>>>(A, Bw, bias, res, C, M, N, K, lda, ldb, ldc,
                                                 nb2, sA1, sA2, sB1, sB2, sC1, sC2, relu);
    else if (mode == 2)
        gemm_tc<1,1,0><<<grid, 256, GEMM_SMEM>>>(A, Bw, bias, res, C, M, N, K, lda, ldb, ldc,
                                                 nb2, sA1, sA2, sB1, sB2, sC1, sC2, relu);
    else
        gemm_tc<0,0,0><<<grid, 256, GEMM_SMEM>>>(A, Bw, bias, res, C, M, N, K, lda, ldb, ldc,
                                                 nb2, sA1, sA2, sB1, sB2, sC1, sC2, relu);
}

extern "C" void kernel_launch(void* const* d_in, const int* in_sizes, int n_in,
                              void* d_out, int out_size)
{
    const float* x_T     = (const float*)d_in[0];
    const float* x_S     = (const float*)d_in[1];
    const float* Wq_t    = (const float*)d_in[2];
    const float* Wk_t    = (const float*)d_in[3];
    const float* Wv_t    = (const float*)d_in[4];
    const float* Wo      = (const float*)d_in[5];
    const float* Wq_s    = (const float*)d_in[6];
    const float* Wk_s    = (const float*)d_in[7];
    const float* ff1_w1  = (const float*)d_in[8];
    const float* ff1_b1  = (const float*)d_in[9];
    const float* ff1_w2  = (const float*)d_in[10];
    const float* ff1_b2  = (const float*)d_in[11];
    const float* ff2_w1  = (const float*)d_in[12];
    const float* ff2_b1  = (const float*)d_in[13];
    const float* ff2_w2  = (const float*)d_in[14];
    const float* ff2_b2  = (const float*)d_in[15];
    const float* t_ln1_w = (const float*)d_in[16];
    const float* t_ln1_b = (const float*)d_in[17];
    const float* t_ln2_w = (const float*)d_in[18];
    const float* t_ln2_b = (const float*)d_in[19];
    const float* s_ln1_w = (const float*)d_in[20];
    const float* s_ln1_b = (const float*)d_in[21];
    const float* fus_ln_w= (const float*)d_in[22];
    const float* fus_ln_b= (const float*)d_in[23];

    float *h, *qkv, *o, *x, *u, *to, *hs, *qks, *x2;
    float *wqkv, *wqks, *wo, *w11, *w12, *w21, *w22;
    cudaGetSymbolAddress((void**)&h,    g_h);
    cudaGetSymbolAddress((void**)&qkv,  g_qkv);
    cudaGetSymbolAddress((void**)&o,    g_o);
    cudaGetSymbolAddress((void**)&x,    g_x);
    cudaGetSymbolAddress((void**)&u,    g_u);
    cudaGetSymbolAddress((void**)&to,   g_to);
    cudaGetSymbolAddress((void**)&hs,   g_hs);
    cudaGetSymbolAddress((void**)&qks,  g_qks);
    cudaGetSymbolAddress((void**)&x2,   g_x2);
    cudaGetSymbolAddress((void**)&wqkv, g_wqkv);
    cudaGetSymbolAddress((void**)&wqks, g_wqks);
    cudaGetSymbolAddress((void**)&wo,   g_wo);
    cudaGetSymbolAddress((void**)&w11,  g_w11);
    cudaGetSymbolAddress((void**)&w12,  g_w12);
    cudaGetSymbolAddress((void**)&w21,  g_w21);
    cudaGetSymbolAddress((void**)&w22,  g_w22);

    float* out = (float*)d_out;                 // [B,T,C]
    float* sw  = out + (long long)ROWS_T * CC;  // spatial_weights [B,C,C]

    cudaFuncSetAttribute(gemm_tc<0,0,0>, cudaFuncAttributeMaxDynamicSharedMemorySize, GEMM_SMEM);
    cudaFuncSetAttribute(gemm_tc<0,0,1>, cudaFuncAttributeMaxDynamicSharedMemorySize, GEMM_SMEM);
    cudaFuncSetAttribute(gemm_tc<1,1,0>, cudaFuncAttributeMaxDynamicSharedMemorySize, GEMM_SMEM);
    cudaFuncSetAttribute(attn_tc, cudaFuncAttributeMaxDynamicSharedMemorySize, ATTN_SMEM);

    // pack + pre-round weights (one node)
    pack_weights<<<262144/256, 256>>>(Wq_t, Wk_t, Wv_t, Wo, Wq_s, Wk_s,
                                      ff1_w1, ff1_w2, ff2_w1, ff2_w2,
                                      wqkv, wqks, wo, w11, w12, w21, w22);

    // ---- temporal branch ----
    ln_warp<2><<<ROWS_T/8, 256>>>(x_T, t_ln1_w, t_ln1_b, h);
    gemm(h, wqkv, 0, 0, qkv, ROWS_T, 768, CC, CC, CC, 768, 1,1, 0,0,0,0,0,0, 0, 1);
    attn_tc<<<dim3(TT/64, BB*HH), 128, ATTN_SMEM>>>(qkv, o);
    gemm(o, wo, 0, x_T, x, ROWS_T, CC, CC, CC, CC, CC, 1,1, 0,0,0,0,0,0, 0, 0);
    ln_warp<2><<<ROWS_T/8, 256>>>(x, t_ln2_w, t_ln2_b, h);
    gemm(h, w11, ff1_b1, 0, u,  ROWS_T, 4*CC, CC, CC, CC, 4*CC, 1,1, 0,0,0,0,0,0, 1, 1);
    gemm(u, w12, ff1_b2, x, to, ROWS_T, CC, 4*CC, 4*CC, 4*CC, CC, 1,1, 0,0,0,0,0,0, 0, 0);

    // ---- spatial branch ----
    ln_warp<4><<<ROWS_S/8, 256>>>(x_S, s_ln1_w, s_ln1_b, hs);
    gemm(hs, wqks, 0, 0, qks, ROWS_S, 1024, TT, TT, TT, 1024, 1,1, 0,0,0,0,0,0, 0, 1);
    spatial_sw<<<256, 256>>>(qks, sw);

    // ---- fusion: x2 = TO + TO @ sw^T (batched over b; to/sw need cvt) ----
    gemm(to, sw, 0, to, x2, TT, CC, CC, CC, CC, CC,
         BB, 1,
         (long long)TT*CC, 0, (long long)CC*CC, 0, (long long)TT*CC, 0, 0, 2);

    // ---- FFN2 -> out ----
    ln_warp<2><<<ROWS_T/8, 256>>>(x2, fus_ln_w, fus_ln_b, h);
    gemm(h, w21, ff2_b1, 0, u, ROWS_T, 4*CC, CC, CC, CC, 4*CC, 1,1, 0,0,0,0,0,0, 1, 1);
    gemm(u, w22, ff2_b2, x2, out, ROWS_T, CC, 4*CC, 4*CC, 4*CC, CC, 1,1, 0,0,0,0,0,0, 0, 0);
}